// round 1
// baseline (speedup 1.0000x reference)
#include <cuda_runtime.h>

#define HW 1024
#define BATCH 8

// Scratch (device globals: no allocation allowed in kernel_launch)
__device__ float g_cat[BATCH * 1024 * HW];   // [y0|y1|y2|y3] concat buffer, 32 MB
__device__ float g_z  [BATCH * 256  * HW];   // conv3x3 output, 8 MB
__device__ float g_qkv[BATCH * 768  * HW];   // qkv conv output, 24 MB
__device__ float g_att[BATCH * 256  * HW];   // attention output, 8 MB

// ---------------------------------------------------------------------------
// Generic 1x1-conv GEMM: out[b,co,p] = epilogue( sum_ci W[co,ci] * X[b,ci,p] )
// Tiles: 64 (co) x 64 (p) x 16 (ci). 256 threads, 4x4 microtile each.
// flags: 1 = BN, 2 = SiLU, 4 = residual add
// ---------------------------------------------------------------------------
__global__ __launch_bounds__(256) void gemm1x1_kernel(
    const float* __restrict__ X, const float* __restrict__ W,
    const float* __restrict__ bn, const float* __restrict__ res,
    float* __restrict__ out,
    int Cin, int Cout,
    long xbStride, long obStride, long rbStride, int flags)
{
    __shared__ float Ws[16][68];
    __shared__ float Xs[16][68];

    const int b   = blockIdx.z;
    const int p0  = blockIdx.x * 64;
    const int co0 = blockIdx.y * 64;
    const int tid = threadIdx.x;
    const int ty  = tid >> 4;    // 0..15 -> output channel group
    const int tx  = tid & 15;    // 0..15 -> pixel group

    const float* Xb = X + (long)b * xbStride;

    float acc[4][4] = {};

    for (int k0 = 0; k0 < Cin; k0 += 16) {
        #pragma unroll
        for (int e = tid; e < 1024; e += 256) {
            int kk = e & 15, co = e >> 4;
            Ws[kk][co] = W[(long)(co0 + co) * Cin + k0 + kk];
        }
        #pragma unroll
        for (int e = tid; e < 1024; e += 256) {
            int p = e & 63, kk = e >> 6;
            Xs[kk][p] = Xb[(long)(k0 + kk) * HW + p0 + p];
        }
        __syncthreads();
        #pragma unroll
        for (int kk = 0; kk < 16; kk++) {
            float4 av4 = *(const float4*)&Ws[kk][ty * 4];
            float4 xv4 = *(const float4*)&Xs[kk][tx * 4];
            float av[4] = {av4.x, av4.y, av4.z, av4.w};
            float xv[4] = {xv4.x, xv4.y, xv4.z, xv4.w};
            #pragma unroll
            for (int i = 0; i < 4; i++)
                #pragma unroll
                for (int j = 0; j < 4; j++)
                    acc[i][j] += av[i] * xv[j];
        }
        __syncthreads();
    }

    #pragma unroll
    for (int i = 0; i < 4; i++) {
        int co = co0 + ty * 4 + i;
        float s = 1.f, c = 0.f;
        if (flags & 1) {
            float g = bn[co], bb = bn[Cout + co];
            float mu = bn[2 * Cout + co], vv = bn[3 * Cout + co];
            s = g * rsqrtf(vv + 1e-3f);
            c = bb - mu * s;
        }
        #pragma unroll
        for (int j = 0; j < 4; j++) {
            int p = p0 + tx * 4 + j;
            float val = acc[i][j] * s + c;
            if (flags & 2) val = val / (1.f + __expf(-val));
            if (flags & 4) val += res[(long)b * rbStride + (long)co * HW + p];
            out[(long)b * obStride + (long)co * HW + p] = val;
        }
    }
}

// ---------------------------------------------------------------------------
// 3x3 conv (pad 1) as implicit GEMM, fused BN+SiLU. Cin=Cout=256, 32x32 image.
// ---------------------------------------------------------------------------
__global__ __launch_bounds__(256) void conv3x3_kernel(
    const float* __restrict__ X, const float* __restrict__ W,
    const float* __restrict__ bn, float* __restrict__ out,
    int Cin, int Cout, long xbStride, long obStride)
{
    __shared__ float Ws[16][68];
    __shared__ float Xs[16][68];

    const int b   = blockIdx.z;
    const int p0  = blockIdx.x * 64;
    const int co0 = blockIdx.y * 64;
    const int tid = threadIdx.x;
    const int ty  = tid >> 4;
    const int tx  = tid & 15;

    const float* Xb = X + (long)b * xbStride;

    float acc[4][4] = {};

    for (int t = 0; t < 9; t++) {
        const int dy = t / 3 - 1, dx = t % 3 - 1;
        for (int k0 = 0; k0 < Cin; k0 += 16) {
            #pragma unroll
            for (int e = tid; e < 1024; e += 256) {
                int kk = e & 15, co = e >> 4;
                Ws[kk][co] = W[((long)(co0 + co) * Cin + k0 + kk) * 9 + t];
            }
            #pragma unroll
            for (int e = tid; e < 1024; e += 256) {
                int p = e & 63, kk = e >> 6;
                int pp  = p0 + p;
                int row = (pp >> 5) + dy;
                int col = (pp & 31) + dx;
                float xv = 0.f;
                if ((unsigned)row < 32u && (unsigned)col < 32u)
                    xv = Xb[(long)(k0 + kk) * HW + row * 32 + col];
                Xs[kk][p] = xv;
            }
            __syncthreads();
            #pragma unroll
            for (int kk = 0; kk < 16; kk++) {
                float4 av4 = *(const float4*)&Ws[kk][ty * 4];
                float4 xv4 = *(const float4*)&Xs[kk][tx * 4];
                float av[4] = {av4.x, av4.y, av4.z, av4.w};
                float xv[4] = {xv4.x, xv4.y, xv4.z, xv4.w};
                #pragma unroll
                for (int i = 0; i < 4; i++)
                    #pragma unroll
                    for (int j = 0; j < 4; j++)
                        acc[i][j] += av[i] * xv[j];
            }
            __syncthreads();
        }
    }

    #pragma unroll
    for (int i = 0; i < 4; i++) {
        int co = co0 + ty * 4 + i;
        float g = bn[co], bb = bn[Cout + co];
        float mu = bn[2 * Cout + co], vv = bn[3 * Cout + co];
        float s = g * rsqrtf(vv + 1e-3f);
        float c = bb - mu * s;
        #pragma unroll
        for (int j = 0; j < 4; j++) {
            int p = p0 + tx * 4 + j;
            float val = acc[i][j] * s + c;
            val = val / (1.f + __expf(-val));
            out[(long)b * obStride + (long)co * HW + p] = val;
        }
    }
}

// ---------------------------------------------------------------------------
// Fused flash attention per (b, h): q,k,v are (64, 1024) slices of g_qkv.
//   kr[d][j] = k[d][j] + rw[d][col(j)] + rh[d][row(j)]
//   logits = q^T kr / 8;  softmax over j;  out[d][i] = sum_j a[i][j] v[d][j]
// Block: 64 q-rows, 256 threads (16x16), online softmax over 16 j-tiles of 64.
// ---------------------------------------------------------------------------
#define IP 68   // padded smem row stride

extern __shared__ float fa_sm[];

__global__ __launch_bounds__(256) void flash_attn_kernel(
    const float* __restrict__ qkv, const float* __restrict__ rw,
    const float* __restrict__ rh, float* __restrict__ out)
{
    float* Qs = fa_sm;               // Qs[d*IP + i]
    float* KV = fa_sm + 64 * IP;     // KR: [d*IP + j], later V: [j*IP + d]
    float* Ps = fa_sm + 128 * IP;    // Ps[j*IP + i]

    const int b  = blockIdx.z;
    const int h  = blockIdx.y;
    const int i0 = blockIdx.x * 64;
    const int tid = threadIdx.x;
    const int ty = tid >> 4;   // q-row group
    const int tx = tid & 15;   // j-col / d-dim group

    const float* qb  = qkv + ((long)b * 768 + h * 64) * HW;
    const float* kb  = qb + 256 * HW;
    const float* vb  = qb + 512 * HW;
    const float* rwh = rw + h * 64 * 32;   // rwh[d*32 + col]
    const float* rhh = rh + h * 64 * 32;   // rhh[d*32 + row]

    // Load Q tile: Qs[d][i]
    #pragma unroll
    for (int e = tid; e < 4096; e += 256) {
        int d = e >> 6, i = e & 63;
        Qs[d * IP + i] = qb[(long)d * HW + i0 + i];
    }

    float m[4], l[4], acc[4][4];
    #pragma unroll
    for (int r = 0; r < 4; r++) {
        m[r] = -1e30f; l[r] = 0.f;
        #pragma unroll
        for (int c = 0; c < 4; c++) acc[r][c] = 0.f;
    }
    __syncthreads();

    for (int j0 = 0; j0 < HW; j0 += 64) {
        // KR tile: KV[d][j] = k + positional bias
        #pragma unroll
        for (int e = tid; e < 4096; e += 256) {
            int d = e >> 6, j = e & 63;
            int jj = j0 + j;
            KV[d * IP + j] = kb[(long)d * HW + jj]
                           + rwh[d * 32 + (jj & 31)]
                           + rhh[d * 32 + (jj >> 5)];
        }
        __syncthreads();

        // S[i][j] = sum_d Q[i][d] * KR[d][j], scaled by 1/8
        float s[4][4] = {};
        #pragma unroll 8
        for (int d = 0; d < 64; d++) {
            float4 a4 = *(const float4*)&Qs[d * IP + ty * 4];
            float4 b4 = *(const float4*)&KV[d * IP + tx * 4];
            float av[4] = {a4.x, a4.y, a4.z, a4.w};
            float bv[4] = {b4.x, b4.y, b4.z, b4.w};
            #pragma unroll
            for (int r = 0; r < 4; r++)
                #pragma unroll
                for (int c = 0; c < 4; c++)
                    s[r][c] += av[r] * bv[c];
        }

        // online softmax update (row stats reduced over the 16 tx lanes)
        #pragma unroll
        for (int r = 0; r < 4; r++) {
            #pragma unroll
            for (int c = 0; c < 4; c++) s[r][c] *= 0.125f;
            float tmax = fmaxf(fmaxf(s[r][0], s[r][1]), fmaxf(s[r][2], s[r][3]));
            #pragma unroll
            for (int o = 8; o; o >>= 1)
                tmax = fmaxf(tmax, __shfl_xor_sync(0xffffffffu, tmax, o));
            float mn = fmaxf(m[r], tmax);
            float corr = __expf(m[r] - mn);
            float rs = 0.f;
            #pragma unroll
            for (int c = 0; c < 4; c++) {
                float p = __expf(s[r][c] - mn);
                s[r][c] = p;
                rs += p;
            }
            #pragma unroll
            for (int o = 8; o; o >>= 1)
                rs += __shfl_xor_sync(0xffffffffu, rs, o);
            l[r] = l[r] * corr + rs;
            m[r] = mn;
            #pragma unroll
            for (int c = 0; c < 4; c++) acc[r][c] *= corr;
        }

        // write P tile (transposed: Ps[j][i])
        #pragma unroll
        for (int r = 0; r < 4; r++)
            #pragma unroll
            for (int c = 0; c < 4; c++)
                Ps[(tx * 4 + c) * IP + ty * 4 + r] = s[r][c];
        __syncthreads();   // all KV reads done; Ps visible

        // V tile: KV[j][d]
        #pragma unroll
        for (int e = tid; e < 4096; e += 256) {
            int d = e >> 6, j = e & 63;
            KV[j * IP + d] = vb[(long)d * HW + j0 + j];
        }
        __syncthreads();

        // acc[i][d] += sum_j P[i][j] * V[d][j]
        #pragma unroll 8
        for (int j = 0; j < 64; j++) {
            float4 a4 = *(const float4*)&Ps[j * IP + ty * 4];
            float4 b4 = *(const float4*)&KV[j * IP + tx * 4];
            float av[4] = {a4.x, a4.y, a4.z, a4.w};
            float bv[4] = {b4.x, b4.y, b4.z, b4.w};
            #pragma unroll
            for (int r = 0; r < 4; r++)
                #pragma unroll
                for (int c = 0; c < 4; c++)
                    acc[r][c] += av[r] * bv[c];
        }
        __syncthreads();   // before next KR fill overwrites KV
    }

    // out[b, h*64 + d, i] = acc / l
    #pragma unroll
    for (int r = 0; r < 4; r++) {
        float inv = 1.f / l[r];
        #pragma unroll
        for (int c = 0; c < 4; c++) {
            int d = tx * 4 + c;
            int i = i0 + ty * 4 + r;
            out[((long)b * 256 + h * 64 + d) * HW + i] = acc[r][c] * inv;
        }
    }
}

// ---------------------------------------------------------------------------
extern "C" void kernel_launch(void* const* d_in, const int* in_sizes, int n_in,
                              void* d_out, int out_size)
{
    const float* x        = (const float*)d_in[0];
    const float* cv1_w    = (const float*)d_in[1];
    const float* cv1_bn   = (const float*)d_in[2];
    const float* cv2_w    = (const float*)d_in[3];
    const float* cv2_bn   = (const float*)d_in[4];
    const float* m_cv1_w  = (const float*)d_in[5];
    const float* m_cv1_bn = (const float*)d_in[6];
    const float* m_qkv_w  = (const float*)d_in[7];
    const float* m_rw     = (const float*)d_in[8];
    const float* m_rh     = (const float*)d_in[9];
    const float* m_cv2_w  = (const float*)d_in[10];
    const float* m_cv2_bn = (const float*)d_in[11];
    float* out = (float*)d_out;

    float *cat, *z, *qkv, *att;
    cudaGetSymbolAddress((void**)&cat, g_cat);
    cudaGetSymbolAddress((void**)&z,   g_z);
    cudaGetSymbolAddress((void**)&qkv, g_qkv);
    cudaGetSymbolAddress((void**)&att, g_att);

    const int FA_SMEM = 3 * 64 * IP * 4;  // 52224 bytes
    cudaFuncSetAttribute(flash_attn_kernel,
                         cudaFuncAttributeMaxDynamicSharedMemorySize, FA_SMEM);

    const long CAT_S = 1024L * HW;

    // cv1: x (512) -> cat channels [0:512)  == [y0 | y1]
    gemm1x1_kernel<<<dim3(16, 8, BATCH), 256>>>(
        x, cv1_w, cv1_bn, nullptr, cat,
        512, 512, 512L * HW, CAT_S, 0, /*BN|SiLU*/ 3);

    for (int i = 0; i < 2; i++) {
        const float* yin = cat + (long)(256 + i * 256) * HW;  // ys[-1]

        // cbs 3x3: yin -> g_z
        conv3x3_kernel<<<dim3(16, 4, BATCH), 256>>>(
            yin, m_cv1_w + (long)i * 256 * 256 * 9, m_cv1_bn + i * 4 * 256,
            z, 256, 256, CAT_S, 256L * HW);

        // qkv 1x1 (no BN, no act): g_z -> g_qkv
        gemm1x1_kernel<<<dim3(16, 12, BATCH), 256>>>(
            z, m_qkv_w + (long)i * 768 * 256, nullptr, nullptr, qkv,
            256, 768, 256L * HW, 768L * HW, 0, 0);

        // attention: g_qkv -> g_att
        flash_attn_kernel<<<dim3(16, 4, BATCH), 256, FA_SMEM>>>(
            qkv, m_rw + i * 8192, m_rh + i * 8192, att);

        // m_cv2 1x1 + BN + SiLU + residual(yin) -> cat channels [512+i*256 : )
        gemm1x1_kernel<<<dim3(16, 4, BATCH), 256>>>(
            att, m_cv2_w + (long)i * 256 * 256, m_cv2_bn + i * 4 * 256,
            yin, cat + (long)(512 + i * 256) * HW,
            256, 256, 256L * HW, CAT_S, CAT_S, /*BN|SiLU|res*/ 7);
    }

    // cv2: cat (1024) -> out (512)
    gemm1x1_kernel<<<dim3(16, 8, BATCH), 256>>>(
        cat, cv2_w, cv2_bn, nullptr, out,
        1024, 512, CAT_S, 512L * HW, 0, 3);
}

// round 2
// speedup vs baseline: 1.9868x; 1.9868x over previous
#include <cuda_runtime.h>
#include <cstdint>

#define HW 1024
#define BATCH 8

// Scratch (device globals: no allocation allowed in kernel_launch)
__device__ float g_cat[BATCH * 1024 * HW];   // [y0|y1|y2|y3] concat buffer
__device__ float g_z  [BATCH * 256  * HW];
__device__ float g_qkv[BATCH * 768  * HW];
__device__ float g_att[BATCH * 256  * HW];
__device__ float g_w3 [2 * 9 * 256 * 256];   // reordered 3x3 weights [i][t][co][ci]

// ---------------------------------------------------------------------------
// tf32 helpers
// ---------------------------------------------------------------------------
__device__ __forceinline__ uint32_t f2tf(float x) {
    uint32_t r;
    asm("cvt.rna.tf32.f32 %0, %1;" : "=r"(r) : "f"(x));
    return r;
}

__device__ __forceinline__ void mma8(float c[4],
    uint32_t a0, uint32_t a1, uint32_t a2, uint32_t a3,
    uint32_t b0, uint32_t b1)
{
    asm volatile(
        "mma.sync.aligned.m16n8k8.row.col.f32.tf32.tf32.f32 "
        "{%0,%1,%2,%3}, {%4,%5,%6,%7}, {%8,%9}, {%0,%1,%2,%3};"
        : "+f"(c[0]), "+f"(c[1]), "+f"(c[2]), "+f"(c[3])
        : "r"(a0), "r"(a1), "r"(a2), "r"(a3), "r"(b0), "r"(b1));
}

#define AST 36    // A smem row stride (floats): (4m+k)%32 distinct -> conflict-free
#define BST 136   // B smem row stride: (8k+n)%32 distinct -> conflict-free

// ---------------------------------------------------------------------------
// Reorder m_cv1_w [i][co][ci][3][3] -> g_w3 [i][t][co][ci]
// ---------------------------------------------------------------------------
__global__ void reorder_w3_kernel(const float* __restrict__ w, float* __restrict__ o)
{
    int idx = blockIdx.x * 256 + threadIdx.x;
    if (idx >= 2 * 9 * 65536) return;
    int i  = idx / (9 * 65536);
    int r  = idx % (9 * 65536);
    int t  = r / 65536;
    int rc = r % 65536;
    int co = rc >> 8, ci = rc & 255;
    o[idx] = w[((long)(i * 256 + co) * 256 + ci) * 9 + t];
}

// ---------------------------------------------------------------------------
// tf32 tensor-core GEMM for 1x1 convs.
// Block tile 128(co) x 128(px), K-chunk 32. 8 warps (2x4), warp tile 64x32.
// flags: 1 = BN, 2 = SiLU, 4 = residual add
// ---------------------------------------------------------------------------
__global__ __launch_bounds__(256) void gemm_tf32_kernel(
    const float* __restrict__ X, const float* __restrict__ W,
    const float* __restrict__ bn, const float* __restrict__ res,
    float* __restrict__ out,
    int Cin, int Cout, long xbS, long obS, long rbS, int flags)
{
    __shared__ uint32_t As[128 * AST];
    __shared__ uint32_t Bs[32 * BST];

    const int b   = blockIdx.z;
    const int p0  = blockIdx.x * 128;
    const int co0 = blockIdx.y * 128;
    const int tid = threadIdx.x;
    const int lane = tid & 31, wid = tid >> 5;
    const int wm = wid >> 2, wn = wid & 3;     // warp grid 2x4

    const float* Xb = X + (long)b * xbS;

    float acc[4][4][4];
    #pragma unroll
    for (int mt = 0; mt < 4; mt++)
        #pragma unroll
        for (int nt = 0; nt < 4; nt++)
            #pragma unroll
            for (int e = 0; e < 4; e++) acc[mt][nt][e] = 0.f;

    for (int k0 = 0; k0 < Cin; k0 += 32) {
        // A tile: W[co0+r][k0+c], 128x32
        #pragma unroll
        for (int it = 0; it < 4; it++) {
            int r = (tid >> 3) + it * 32;
            int c = (tid & 7) * 4;
            float4 v = *(const float4*)&W[(long)(co0 + r) * Cin + k0 + c];
            As[r * AST + c + 0] = f2tf(v.x);
            As[r * AST + c + 1] = f2tf(v.y);
            As[r * AST + c + 2] = f2tf(v.z);
            As[r * AST + c + 3] = f2tf(v.w);
        }
        // B tile: X[k0+kk][p0+pp], 32x128
        #pragma unroll
        for (int it = 0; it < 4; it++) {
            int kk = (tid >> 5) + it * 8;
            int pp = lane * 4;
            float4 v = *(const float4*)&Xb[(long)(k0 + kk) * HW + p0 + pp];
            Bs[kk * BST + pp + 0] = f2tf(v.x);
            Bs[kk * BST + pp + 1] = f2tf(v.y);
            Bs[kk * BST + pp + 2] = f2tf(v.z);
            Bs[kk * BST + pp + 3] = f2tf(v.w);
        }
        __syncthreads();

        #pragma unroll
        for (int ks = 0; ks < 4; ks++) {
            uint32_t a[4][4], bb[4][2];
            int ar = wm * 64 + (lane >> 2);
            int ac = ks * 8 + (lane & 3);
            #pragma unroll
            for (int mt = 0; mt < 4; mt++) {
                int r = ar + mt * 16;
                a[mt][0] = As[r * AST + ac];
                a[mt][1] = As[(r + 8) * AST + ac];
                a[mt][2] = As[r * AST + ac + 4];
                a[mt][3] = As[(r + 8) * AST + ac + 4];
            }
            int br = ks * 8 + (lane & 3);
            int bc = wn * 32 + (lane >> 2);
            #pragma unroll
            for (int nt = 0; nt < 4; nt++) {
                bb[nt][0] = Bs[br * BST + bc + nt * 8];
                bb[nt][1] = Bs[(br + 4) * BST + bc + nt * 8];
            }
            #pragma unroll
            for (int mt = 0; mt < 4; mt++)
                #pragma unroll
                for (int nt = 0; nt < 4; nt++)
                    mma8(acc[mt][nt], a[mt][0], a[mt][1], a[mt][2], a[mt][3],
                         bb[nt][0], bb[nt][1]);
        }
        __syncthreads();
    }

    // Epilogue
    #pragma unroll
    for (int mt = 0; mt < 4; mt++) {
        int r0 = co0 + wm * 64 + mt * 16 + (lane >> 2);
        int r1 = r0 + 8;
        float s0 = 1.f, c0 = 0.f, s1 = 1.f, c1 = 0.f;
        if (flags & 1) {
            float g0 = bn[r0], b0v = bn[Cout + r0], m0 = bn[2*Cout + r0], v0 = bn[3*Cout + r0];
            s0 = g0 * rsqrtf(v0 + 1e-3f); c0 = b0v - m0 * s0;
            float g1 = bn[r1], b1v = bn[Cout + r1], m1 = bn[2*Cout + r1], v1 = bn[3*Cout + r1];
            s1 = g1 * rsqrtf(v1 + 1e-3f); c1 = b1v - m1 * s1;
        }
        #pragma unroll
        for (int nt = 0; nt < 4; nt++) {
            int col = p0 + wn * 32 + nt * 8 + 2 * (lane & 3);
            float v00 = acc[mt][nt][0] * s0 + c0;
            float v01 = acc[mt][nt][1] * s0 + c0;
            float v10 = acc[mt][nt][2] * s1 + c1;
            float v11 = acc[mt][nt][3] * s1 + c1;
            if (flags & 2) {
                v00 = v00 / (1.f + __expf(-v00));
                v01 = v01 / (1.f + __expf(-v01));
                v10 = v10 / (1.f + __expf(-v10));
                v11 = v11 / (1.f + __expf(-v11));
            }
            if (flags & 4) {
                const float* rb = res + (long)b * rbS;
                v00 += rb[(long)r0 * HW + col];
                v01 += rb[(long)r0 * HW + col + 1];
                v10 += rb[(long)r1 * HW + col];
                v11 += rb[(long)r1 * HW + col + 1];
            }
            float* ob = out + (long)b * obS;
            *(float2*)&ob[(long)r0 * HW + col] = make_float2(v00, v01);
            *(float2*)&ob[(long)r1 * HW + col] = make_float2(v10, v11);
        }
    }
}

// ---------------------------------------------------------------------------
// tf32 tensor-core 3x3 conv (pad 1), Cin=Cout=256, 32x32 image, BN+SiLU.
// Weights pre-reordered to [t][co][ci]. Block tile 128x128.
// ---------------------------------------------------------------------------
__global__ __launch_bounds__(256) void conv3_tf32_kernel(
    const float* __restrict__ X, const float* __restrict__ Wt,
    const float* __restrict__ bn, float* __restrict__ out,
    long xbS, long obS)
{
    __shared__ uint32_t As[128 * AST];
    __shared__ uint32_t Bs[32 * BST];

    const int b   = blockIdx.z;
    const int p0  = blockIdx.x * 128;
    const int co0 = blockIdx.y * 128;
    const int tid = threadIdx.x;
    const int lane = tid & 31, wid = tid >> 5;
    const int wm = wid >> 2, wn = wid & 3;

    const float* Xb = X + (long)b * xbS;

    float acc[4][4][4];
    #pragma unroll
    for (int mt = 0; mt < 4; mt++)
        #pragma unroll
        for (int nt = 0; nt < 4; nt++)
            #pragma unroll
            for (int e = 0; e < 4; e++) acc[mt][nt][e] = 0.f;

    for (int t = 0; t < 9; t++) {
        const int dy = t / 3 - 1, dx = t % 3 - 1;
        const float* Wtt = Wt + t * 65536;
        for (int k0 = 0; k0 < 256; k0 += 32) {
            #pragma unroll
            for (int it = 0; it < 4; it++) {
                int r = (tid >> 3) + it * 32;
                int c = (tid & 7) * 4;
                float4 v = *(const float4*)&Wtt[(long)(co0 + r) * 256 + k0 + c];
                As[r * AST + c + 0] = f2tf(v.x);
                As[r * AST + c + 1] = f2tf(v.y);
                As[r * AST + c + 2] = f2tf(v.z);
                As[r * AST + c + 3] = f2tf(v.w);
            }
            #pragma unroll
            for (int e = tid; e < 4096; e += 256) {
                int kk = e >> 7, p = e & 127;
                int pix = p0 + p;
                int row = (pix >> 5) + dy;
                int col = (pix & 31) + dx;
                float xv = 0.f;
                if ((unsigned)row < 32u && (unsigned)col < 32u)
                    xv = Xb[(long)(k0 + kk) * HW + row * 32 + col];
                Bs[kk * BST + p] = f2tf(xv);
            }
            __syncthreads();

            #pragma unroll
            for (int ks = 0; ks < 4; ks++) {
                uint32_t a[4][4], bb[4][2];
                int ar = wm * 64 + (lane >> 2);
                int ac = ks * 8 + (lane & 3);
                #pragma unroll
                for (int mt = 0; mt < 4; mt++) {
                    int r = ar + mt * 16;
                    a[mt][0] = As[r * AST + ac];
                    a[mt][1] = As[(r + 8) * AST + ac];
                    a[mt][2] = As[r * AST + ac + 4];
                    a[mt][3] = As[(r + 8) * AST + ac + 4];
                }
                int br = ks * 8 + (lane & 3);
                int bc = wn * 32 + (lane >> 2);
                #pragma unroll
                for (int nt = 0; nt < 4; nt++) {
                    bb[nt][0] = Bs[br * BST + bc + nt * 8];
                    bb[nt][1] = Bs[(br + 4) * BST + bc + nt * 8];
                }
                #pragma unroll
                for (int mt = 0; mt < 4; mt++)
                    #pragma unroll
                    for (int nt = 0; nt < 4; nt++)
                        mma8(acc[mt][nt], a[mt][0], a[mt][1], a[mt][2], a[mt][3],
                             bb[nt][0], bb[nt][1]);
            }
            __syncthreads();
        }
    }

    #pragma unroll
    for (int mt = 0; mt < 4; mt++) {
        int r0 = co0 + wm * 64 + mt * 16 + (lane >> 2);
        int r1 = r0 + 8;
        float g0 = bn[r0], b0v = bn[256 + r0], m0 = bn[512 + r0], v0 = bn[768 + r0];
        float s0 = g0 * rsqrtf(v0 + 1e-3f), c0 = b0v - m0 * s0;
        float g1 = bn[r1], b1v = bn[256 + r1], m1 = bn[512 + r1], v1 = bn[768 + r1];
        float s1 = g1 * rsqrtf(v1 + 1e-3f), c1 = b1v - m1 * s1;
        #pragma unroll
        for (int nt = 0; nt < 4; nt++) {
            int col = p0 + wn * 32 + nt * 8 + 2 * (lane & 3);
            float v00 = acc[mt][nt][0] * s0 + c0;
            float v01 = acc[mt][nt][1] * s0 + c0;
            float v10 = acc[mt][nt][2] * s1 + c1;
            float v11 = acc[mt][nt][3] * s1 + c1;
            v00 = v00 / (1.f + __expf(-v00));
            v01 = v01 / (1.f + __expf(-v01));
            v10 = v10 / (1.f + __expf(-v10));
            v11 = v11 / (1.f + __expf(-v11));
            float* ob = out + (long)b * obS;
            *(float2*)&ob[(long)r0 * HW + col] = make_float2(v00, v01);
            *(float2*)&ob[(long)r1 * HW + col] = make_float2(v10, v11);
        }
    }
}

// ---------------------------------------------------------------------------
// Fused flash attention (unchanged from round 1, fp32 SIMT).
// ---------------------------------------------------------------------------
#define IP 68

extern __shared__ float fa_sm[];

__global__ __launch_bounds__(256) void flash_attn_kernel(
    const float* __restrict__ qkv, const float* __restrict__ rw,
    const float* __restrict__ rh, float* __restrict__ out)
{
    float* Qs = fa_sm;
    float* KV = fa_sm + 64 * IP;
    float* Ps = fa_sm + 128 * IP;

    const int b  = blockIdx.z;
    const int h  = blockIdx.y;
    const int i0 = blockIdx.x * 64;
    const int tid = threadIdx.x;
    const int ty = tid >> 4;
    const int tx = tid & 15;

    const float* qb  = qkv + ((long)b * 768 + h * 64) * HW;
    const float* kb  = qb + 256 * HW;
    const float* vb  = qb + 512 * HW;
    const float* rwh = rw + h * 64 * 32;
    const float* rhh = rh + h * 64 * 32;

    #pragma unroll
    for (int e = tid; e < 4096; e += 256) {
        int d = e >> 6, i = e & 63;
        Qs[d * IP + i] = qb[(long)d * HW + i0 + i];
    }

    float m[4], l[4], acc[4][4];
    #pragma unroll
    for (int r = 0; r < 4; r++) {
        m[r] = -1e30f; l[r] = 0.f;
        #pragma unroll
        for (int c = 0; c < 4; c++) acc[r][c] = 0.f;
    }
    __syncthreads();

    for (int j0 = 0; j0 < HW; j0 += 64) {
        #pragma unroll
        for (int e = tid; e < 4096; e += 256) {
            int d = e >> 6, j = e & 63;
            int jj = j0 + j;
            KV[d * IP + j] = kb[(long)d * HW + jj]
                           + rwh[d * 32 + (jj & 31)]
                           + rhh[d * 32 + (jj >> 5)];
        }
        __syncthreads();

        float s[4][4] = {};
        #pragma unroll 8
        for (int d = 0; d < 64; d++) {
            float4 a4 = *(const float4*)&Qs[d * IP + ty * 4];
            float4 b4 = *(const float4*)&KV[d * IP + tx * 4];
            float av[4] = {a4.x, a4.y, a4.z, a4.w};
            float bv[4] = {b4.x, b4.y, b4.z, b4.w};
            #pragma unroll
            for (int r = 0; r < 4; r++)
                #pragma unroll
                for (int c = 0; c < 4; c++)
                    s[r][c] += av[r] * bv[c];
        }

        #pragma unroll
        for (int r = 0; r < 4; r++) {
            #pragma unroll
            for (int c = 0; c < 4; c++) s[r][c] *= 0.125f;
            float tmax = fmaxf(fmaxf(s[r][0], s[r][1]), fmaxf(s[r][2], s[r][3]));
            #pragma unroll
            for (int o = 8; o; o >>= 1)
                tmax = fmaxf(tmax, __shfl_xor_sync(0xffffffffu, tmax, o));
            float mn = fmaxf(m[r], tmax);
            float corr = __expf(m[r] - mn);
            float rs = 0.f;
            #pragma unroll
            for (int c = 0; c < 4; c++) {
                float p = __expf(s[r][c] - mn);
                s[r][c] = p;
                rs += p;
            }
            #pragma unroll
            for (int o = 8; o; o >>= 1)
                rs += __shfl_xor_sync(0xffffffffu, rs, o);
            l[r] = l[r] * corr + rs;
            m[r] = mn;
            #pragma unroll
            for (int c = 0; c < 4; c++) acc[r][c] *= corr;
        }

        #pragma unroll
        for (int r = 0; r < 4; r++)
            #pragma unroll
            for (int c = 0; c < 4; c++)
                Ps[(tx * 4 + c) * IP + ty * 4 + r] = s[r][c];
        __syncthreads();

        #pragma unroll
        for (int e = tid; e < 4096; e += 256) {
            int d = e >> 6, j = e & 63;
            KV[j * IP + d] = vb[(long)d * HW + j0 + j];
        }
        __syncthreads();

        #pragma unroll 8
        for (int j = 0; j < 64; j++) {
            float4 a4 = *(const float4*)&Ps[j * IP + ty * 4];
            float4 b4 = *(const float4*)&KV[j * IP + tx * 4];
            float av[4] = {a4.x, a4.y, a4.z, a4.w};
            float bv[4] = {b4.x, b4.y, b4.z, b4.w};
            #pragma unroll
            for (int r = 0; r < 4; r++)
                #pragma unroll
                for (int c = 0; c < 4; c++)
                    acc[r][c] += av[r] * bv[c];
        }
        __syncthreads();
    }

    #pragma unroll
    for (int r = 0; r < 4; r++) {
        float inv = 1.f / l[r];
        #pragma unroll
        for (int c = 0; c < 4; c++) {
            int d = tx * 4 + c;
            int i = i0 + ty * 4 + r;
            out[((long)b * 256 + h * 64 + d) * HW + i] = acc[r][c] * inv;
        }
    }
}

// ---------------------------------------------------------------------------
extern "C" void kernel_launch(void* const* d_in, const int* in_sizes, int n_in,
                              void* d_out, int out_size)
{
    const float* x        = (const float*)d_in[0];
    const float* cv1_w    = (const float*)d_in[1];
    const float* cv1_bn   = (const float*)d_in[2];
    const float* cv2_w    = (const float*)d_in[3];
    const float* cv2_bn   = (const float*)d_in[4];
    const float* m_cv1_w  = (const float*)d_in[5];
    const float* m_cv1_bn = (const float*)d_in[6];
    const float* m_qkv_w  = (const float*)d_in[7];
    const float* m_rw     = (const float*)d_in[8];
    const float* m_rh     = (const float*)d_in[9];
    const float* m_cv2_w  = (const float*)d_in[10];
    const float* m_cv2_bn = (const float*)d_in[11];
    float* out = (float*)d_out;

    float *cat, *z, *qkv, *att, *w3;
    cudaGetSymbolAddress((void**)&cat, g_cat);
    cudaGetSymbolAddress((void**)&z,   g_z);
    cudaGetSymbolAddress((void**)&qkv, g_qkv);
    cudaGetSymbolAddress((void**)&att, g_att);
    cudaGetSymbolAddress((void**)&w3,  g_w3);

    const int FA_SMEM = 3 * 64 * IP * 4;
    cudaFuncSetAttribute(flash_attn_kernel,
                         cudaFuncAttributeMaxDynamicSharedMemorySize, FA_SMEM);

    const long CAT_S = 1024L * HW;

    // reorder 3x3 weights once per launch (cheap; graph-capturable)
    reorder_w3_kernel<<<(2 * 9 * 65536 + 255) / 256, 256>>>(m_cv1_w, w3);

    // cv1: x (512) -> cat[0:512)
    gemm_tf32_kernel<<<dim3(8, 4, BATCH), 256>>>(
        x, cv1_w, cv1_bn, nullptr, cat,
        512, 512, 512L * HW, CAT_S, 0, 3);

    for (int i = 0; i < 2; i++) {
        const float* yin = cat + (long)(256 + i * 256) * HW;

        conv3_tf32_kernel<<<dim3(8, 2, BATCH), 256>>>(
            yin, w3 + (long)i * 9 * 65536, m_cv1_bn + i * 4 * 256,
            z, CAT_S, 256L * HW);

        gemm_tf32_kernel<<<dim3(8, 6, BATCH), 256>>>(
            z, m_qkv_w + (long)i * 768 * 256, nullptr, nullptr, qkv,
            256, 768, 256L * HW, 768L * HW, 0, 0);

        flash_attn_kernel<<<dim3(16, 4, BATCH), 256, FA_SMEM>>>(
            qkv, m_rw + i * 8192, m_rh + i * 8192, att);

        gemm_tf32_kernel<<<dim3(8, 2, BATCH), 256>>>(
            att, m_cv2_w + (long)i * 256 * 256, m_cv2_bn + i * 4 * 256,
            yin, cat + (long)(512 + i * 256) * HW,
            256, 256, 256L * HW, CAT_S, CAT_S, 7);
    }

    // cv2: cat (1024) -> out (512)
    gemm_tf32_kernel<<<dim3(8, 4, BATCH), 256>>>(
        cat, cv2_w, cv2_bn, nullptr, out,
        1024, 512, CAT_S, 512L * HW, 0, 3);
}

// round 3
// speedup vs baseline: 2.8466x; 1.4327x over previous
#include <cuda_runtime.h>
#include <cstdint>

#define HW 1024
#define BATCH 8

// Scratch (device globals: no allocation allowed in kernel_launch)
__device__ float g_cat[BATCH * 1024 * HW];   // [y0|y1|y2|y3] concat buffer
__device__ float g_z  [BATCH * 256  * HW];
__device__ float g_qkv[BATCH * 768  * HW];
__device__ float g_att[BATCH * 256  * HW];
__device__ float g_w3 [2 * 9 * 256 * 256];   // reordered 3x3 weights [i][t][co][ci]

// ---------------------------------------------------------------------------
// tf32 helpers
// ---------------------------------------------------------------------------
__device__ __forceinline__ uint32_t f2tf(float x) {
    uint32_t r;
    asm("cvt.rna.tf32.f32 %0, %1;" : "=r"(r) : "f"(x));
    return r;
}

__device__ __forceinline__ void mma8(float c[4],
    uint32_t a0, uint32_t a1, uint32_t a2, uint32_t a3,
    uint32_t b0, uint32_t b1)
{
    asm volatile(
        "mma.sync.aligned.m16n8k8.row.col.f32.tf32.tf32.f32 "
        "{%0,%1,%2,%3}, {%4,%5,%6,%7}, {%8,%9}, {%0,%1,%2,%3};"
        : "+f"(c[0]), "+f"(c[1]), "+f"(c[2]), "+f"(c[3])
        : "r"(a0), "r"(a1), "r"(a2), "r"(a3), "r"(b0), "r"(b1));
}

#define AST 36
#define BST 136

// ---------------------------------------------------------------------------
// Reorder m_cv1_w [i][co][ci][3][3] -> g_w3 [i][t][co][ci]
// ---------------------------------------------------------------------------
__global__ void reorder_w3_kernel(const float* __restrict__ w, float* __restrict__ o)
{
    int idx = blockIdx.x * 256 + threadIdx.x;
    if (idx >= 2 * 9 * 65536) return;
    int i  = idx / (9 * 65536);
    int r  = idx % (9 * 65536);
    int t  = r / 65536;
    int rc = r % 65536;
    int co = rc >> 8, ci = rc & 255;
    o[idx] = w[((long)(i * 256 + co) * 256 + ci) * 9 + t];
}

// ---------------------------------------------------------------------------
// tf32 tensor-core GEMM for 1x1 convs (unchanged from round 2).
// ---------------------------------------------------------------------------
__global__ __launch_bounds__(256) void gemm_tf32_kernel(
    const float* __restrict__ X, const float* __restrict__ W,
    const float* __restrict__ bn, const float* __restrict__ res,
    float* __restrict__ out,
    int Cin, int Cout, long xbS, long obS, long rbS, int flags)
{
    __shared__ uint32_t As[128 * AST];
    __shared__ uint32_t Bs[32 * BST];

    const int b   = blockIdx.z;
    const int p0  = blockIdx.x * 128;
    const int co0 = blockIdx.y * 128;
    const int tid = threadIdx.x;
    const int lane = tid & 31, wid = tid >> 5;
    const int wm = wid >> 2, wn = wid & 3;

    const float* Xb = X + (long)b * xbS;

    float acc[4][4][4];
    #pragma unroll
    for (int mt = 0; mt < 4; mt++)
        #pragma unroll
        for (int nt = 0; nt < 4; nt++)
            #pragma unroll
            for (int e = 0; e < 4; e++) acc[mt][nt][e] = 0.f;

    for (int k0 = 0; k0 < Cin; k0 += 32) {
        #pragma unroll
        for (int it = 0; it < 4; it++) {
            int r = (tid >> 3) + it * 32;
            int c = (tid & 7) * 4;
            float4 v = *(const float4*)&W[(long)(co0 + r) * Cin + k0 + c];
            As[r * AST + c + 0] = f2tf(v.x);
            As[r * AST + c + 1] = f2tf(v.y);
            As[r * AST + c + 2] = f2tf(v.z);
            As[r * AST + c + 3] = f2tf(v.w);
        }
        #pragma unroll
        for (int it = 0; it < 4; it++) {
            int kk = (tid >> 5) + it * 8;
            int pp = lane * 4;
            float4 v = *(const float4*)&Xb[(long)(k0 + kk) * HW + p0 + pp];
            Bs[kk * BST + pp + 0] = f2tf(v.x);
            Bs[kk * BST + pp + 1] = f2tf(v.y);
            Bs[kk * BST + pp + 2] = f2tf(v.z);
            Bs[kk * BST + pp + 3] = f2tf(v.w);
        }
        __syncthreads();

        #pragma unroll
        for (int ks = 0; ks < 4; ks++) {
            uint32_t a[4][4], bb[4][2];
            int ar = wm * 64 + (lane >> 2);
            int ac = ks * 8 + (lane & 3);
            #pragma unroll
            for (int mt = 0; mt < 4; mt++) {
                int r = ar + mt * 16;
                a[mt][0] = As[r * AST + ac];
                a[mt][1] = As[(r + 8) * AST + ac];
                a[mt][2] = As[r * AST + ac + 4];
                a[mt][3] = As[(r + 8) * AST + ac + 4];
            }
            int br = ks * 8 + (lane & 3);
            int bc = wn * 32 + (lane >> 2);
            #pragma unroll
            for (int nt = 0; nt < 4; nt++) {
                bb[nt][0] = Bs[br * BST + bc + nt * 8];
                bb[nt][1] = Bs[(br + 4) * BST + bc + nt * 8];
            }
            #pragma unroll
            for (int mt = 0; mt < 4; mt++)
                #pragma unroll
                for (int nt = 0; nt < 4; nt++)
                    mma8(acc[mt][nt], a[mt][0], a[mt][1], a[mt][2], a[mt][3],
                         bb[nt][0], bb[nt][1]);
        }
        __syncthreads();
    }

    #pragma unroll
    for (int mt = 0; mt < 4; mt++) {
        int r0 = co0 + wm * 64 + mt * 16 + (lane >> 2);
        int r1 = r0 + 8;
        float s0 = 1.f, c0 = 0.f, s1 = 1.f, c1 = 0.f;
        if (flags & 1) {
            float g0 = bn[r0], b0v = bn[Cout + r0], m0 = bn[2*Cout + r0], v0 = bn[3*Cout + r0];
            s0 = g0 * rsqrtf(v0 + 1e-3f); c0 = b0v - m0 * s0;
            float g1 = bn[r1], b1v = bn[Cout + r1], m1 = bn[2*Cout + r1], v1 = bn[3*Cout + r1];
            s1 = g1 * rsqrtf(v1 + 1e-3f); c1 = b1v - m1 * s1;
        }
        #pragma unroll
        for (int nt = 0; nt < 4; nt++) {
            int col = p0 + wn * 32 + nt * 8 + 2 * (lane & 3);
            float v00 = acc[mt][nt][0] * s0 + c0;
            float v01 = acc[mt][nt][1] * s0 + c0;
            float v10 = acc[mt][nt][2] * s1 + c1;
            float v11 = acc[mt][nt][3] * s1 + c1;
            if (flags & 2) {
                v00 = v00 / (1.f + __expf(-v00));
                v01 = v01 / (1.f + __expf(-v01));
                v10 = v10 / (1.f + __expf(-v10));
                v11 = v11 / (1.f + __expf(-v11));
            }
            if (flags & 4) {
                const float* rb = res + (long)b * rbS;
                v00 += rb[(long)r0 * HW + col];
                v01 += rb[(long)r0 * HW + col + 1];
                v10 += rb[(long)r1 * HW + col];
                v11 += rb[(long)r1 * HW + col + 1];
            }
            float* ob = out + (long)b * obS;
            *(float2*)&ob[(long)r0 * HW + col] = make_float2(v00, v01);
            *(float2*)&ob[(long)r1 * HW + col] = make_float2(v10, v11);
        }
    }
}

// ---------------------------------------------------------------------------
// tf32 tensor-core 3x3 conv (unchanged from round 2).
// ---------------------------------------------------------------------------
__global__ __launch_bounds__(256) void conv3_tf32_kernel(
    const float* __restrict__ X, const float* __restrict__ Wt,
    const float* __restrict__ bn, float* __restrict__ out,
    long xbS, long obS)
{
    __shared__ uint32_t As[128 * AST];
    __shared__ uint32_t Bs[32 * BST];

    const int b   = blockIdx.z;
    const int p0  = blockIdx.x * 128;
    const int co0 = blockIdx.y * 128;
    const int tid = threadIdx.x;
    const int lane = tid & 31, wid = tid >> 5;
    const int wm = wid >> 2, wn = wid & 3;

    const float* Xb = X + (long)b * xbS;

    float acc[4][4][4];
    #pragma unroll
    for (int mt = 0; mt < 4; mt++)
        #pragma unroll
        for (int nt = 0; nt < 4; nt++)
            #pragma unroll
            for (int e = 0; e < 4; e++) acc[mt][nt][e] = 0.f;

    for (int t = 0; t < 9; t++) {
        const int dy = t / 3 - 1, dx = t % 3 - 1;
        const float* Wtt = Wt + t * 65536;
        for (int k0 = 0; k0 < 256; k0 += 32) {
            #pragma unroll
            for (int it = 0; it < 4; it++) {
                int r = (tid >> 3) + it * 32;
                int c = (tid & 7) * 4;
                float4 v = *(const float4*)&Wtt[(long)(co0 + r) * 256 + k0 + c];
                As[r * AST + c + 0] = f2tf(v.x);
                As[r * AST + c + 1] = f2tf(v.y);
                As[r * AST + c + 2] = f2tf(v.z);
                As[r * AST + c + 3] = f2tf(v.w);
            }
            #pragma unroll
            for (int e = tid; e < 4096; e += 256) {
                int kk = e >> 7, p = e & 127;
                int pix = p0 + p;
                int row = (pix >> 5) + dy;
                int col = (pix & 31) + dx;
                float xv = 0.f;
                if ((unsigned)row < 32u && (unsigned)col < 32u)
                    xv = Xb[(long)(k0 + kk) * HW + row * 32 + col];
                Bs[kk * BST + p] = f2tf(xv);
            }
            __syncthreads();

            #pragma unroll
            for (int ks = 0; ks < 4; ks++) {
                uint32_t a[4][4], bb[4][2];
                int ar = wm * 64 + (lane >> 2);
                int ac = ks * 8 + (lane & 3);
                #pragma unroll
                for (int mt = 0; mt < 4; mt++) {
                    int r = ar + mt * 16;
                    a[mt][0] = As[r * AST + ac];
                    a[mt][1] = As[(r + 8) * AST + ac];
                    a[mt][2] = As[r * AST + ac + 4];
                    a[mt][3] = As[(r + 8) * AST + ac + 4];
                }
                int br = ks * 8 + (lane & 3);
                int bc = wn * 32 + (lane >> 2);
                #pragma unroll
                for (int nt = 0; nt < 4; nt++) {
                    bb[nt][0] = Bs[br * BST + bc + nt * 8];
                    bb[nt][1] = Bs[(br + 4) * BST + bc + nt * 8];
                }
                #pragma unroll
                for (int mt = 0; mt < 4; mt++)
                    #pragma unroll
                    for (int nt = 0; nt < 4; nt++)
                        mma8(acc[mt][nt], a[mt][0], a[mt][1], a[mt][2], a[mt][3],
                             bb[nt][0], bb[nt][1]);
            }
            __syncthreads();
        }
    }

    #pragma unroll
    for (int mt = 0; mt < 4; mt++) {
        int r0 = co0 + wm * 64 + mt * 16 + (lane >> 2);
        int r1 = r0 + 8;
        float g0 = bn[r0], b0v = bn[256 + r0], m0 = bn[512 + r0], v0 = bn[768 + r0];
        float s0 = g0 * rsqrtf(v0 + 1e-3f), c0 = b0v - m0 * s0;
        float g1 = bn[r1], b1v = bn[256 + r1], m1 = bn[512 + r1], v1 = bn[768 + r1];
        float s1 = g1 * rsqrtf(v1 + 1e-3f), c1 = b1v - m1 * s1;
        #pragma unroll
        for (int nt = 0; nt < 4; nt++) {
            int col = p0 + wn * 32 + nt * 8 + 2 * (lane & 3);
            float v00 = acc[mt][nt][0] * s0 + c0;
            float v01 = acc[mt][nt][1] * s0 + c0;
            float v10 = acc[mt][nt][2] * s1 + c1;
            float v11 = acc[mt][nt][3] * s1 + c1;
            v00 = v00 / (1.f + __expf(-v00));
            v01 = v01 / (1.f + __expf(-v01));
            v10 = v10 / (1.f + __expf(-v10));
            v11 = v11 / (1.f + __expf(-v11));
            float* ob = out + (long)b * obS;
            *(float2*)&ob[(long)r0 * HW + col] = make_float2(v00, v01);
            *(float2*)&ob[(long)r1 * HW + col] = make_float2(v10, v11);
        }
    }
}

// ---------------------------------------------------------------------------
// tf32 tensor-core flash attention.
// Block: one (b,h), 64 q-rows; 8 warps = 4 (i-strips of 16) x 2 (j/d halves).
// j-tiles of 64. Q/KR/V/P stored in smem as tf32 bits.
// Strides (mod 32): Qs/KRs 72 (->8), Vs/Ps 68 (->4): all fragment reads
// conflict-free.
// ---------------------------------------------------------------------------
#define QST 72
#define VST 68
#define FA_Q   0
#define FA_KR  (64 * QST)
#define FA_V   (FA_KR + 64 * QST)
#define FA_P   (FA_V + 64 * VST)
#define FA_RED (FA_P + 64 * VST)              // float red_max[128], red_sum[128]
#define FA_TOT (FA_RED + 256)                 // u32 units

extern __shared__ uint32_t fa_u[];

__global__ __launch_bounds__(256) void flash_tf32_kernel(
    const float* __restrict__ qkv, const float* __restrict__ rw,
    const float* __restrict__ rh, float* __restrict__ out)
{
    uint32_t* Qs  = fa_u + FA_Q;
    uint32_t* KRs = fa_u + FA_KR;
    uint32_t* Vs  = fa_u + FA_V;
    uint32_t* Ps  = fa_u + FA_P;
    float* red_max = (float*)(fa_u + FA_RED);
    float* red_sum = red_max + 128;

    const int b  = blockIdx.z;
    const int h  = blockIdx.y;
    const int i0 = blockIdx.x * 64;
    const int tid  = threadIdx.x;
    const int lane = tid & 31, wid = tid >> 5;
    const int wm = wid >> 1;          // 0..3: i-strip (16 rows)
    const int wn = wid & 1;           // 0..1: 32-col half (j for S, d for O)
    const int lq = lane >> 2;         // 0..7
    const int lr = lane & 3;          // 0..3

    const float* qb  = qkv + ((long)b * 768 + h * 64) * HW;
    const float* kb  = qb + 256 * HW;
    const float* vb  = qb + 512 * HW;
    const float* rwh = rw + h * 64 * 32;
    const float* rhh = rh + h * 64 * 32;

    // Q tile -> smem (tf32), layout [d][i]
    #pragma unroll
    for (int e = tid; e < 4096; e += 256) {
        int d = e >> 6, i = e & 63;
        Qs[d * QST + i] = f2tf(qb[(long)d * HW + i0 + i]);
    }

    const int row_lo = wm * 16 + lq;      // block-local q row
    const int row_hi = row_lo + 8;

    float m_lo = -1e30f, m_hi = -1e30f, l_lo = 0.f, l_hi = 0.f;
    float accO[4][4];
    #pragma unroll
    for (int nt = 0; nt < 4; nt++)
        #pragma unroll
        for (int e = 0; e < 4; e++) accO[nt][e] = 0.f;

    __syncthreads();

    for (int j0 = 0; j0 < HW; j0 += 64) {
        // KR tile [d][j] and V tile [d][j]
        #pragma unroll
        for (int e = tid; e < 4096; e += 256) {
            int d = e >> 6, j = e & 63;
            int jj = j0 + j;
            float krv = kb[(long)d * HW + jj]
                      + rwh[d * 32 + (jj & 31)]
                      + rhh[d * 32 + (jj >> 5)];
            KRs[d * QST + j] = f2tf(krv);
            Vs[d * VST + j]  = f2tf(vb[(long)d * HW + jj]);
        }
        __syncthreads();

        // S = Q^T * KR  (M=64 i, N=64 j, K=64 d)
        float s[4][4];
        #pragma unroll
        for (int nt = 0; nt < 4; nt++)
            #pragma unroll
            for (int e = 0; e < 4; e++) s[nt][e] = 0.f;

        #pragma unroll
        for (int ks = 0; ks < 8; ks++) {
            int d0 = ks * 8 + lr;
            uint32_t a0 = Qs[d0 * QST + row_lo];
            uint32_t a1 = Qs[d0 * QST + row_hi];
            uint32_t a2 = Qs[(d0 + 4) * QST + row_lo];
            uint32_t a3 = Qs[(d0 + 4) * QST + row_hi];
            #pragma unroll
            for (int nt = 0; nt < 4; nt++) {
                int jc = wn * 32 + nt * 8 + lq;
                uint32_t b0 = KRs[d0 * QST + jc];
                uint32_t b1 = KRs[(d0 + 4) * QST + jc];
                mma8(s[nt], a0, a1, a2, a3, b0, b1);
            }
        }

        // scale logits
        #pragma unroll
        for (int nt = 0; nt < 4; nt++)
            #pragma unroll
            for (int e = 0; e < 4; e++) s[nt][e] *= 0.125f;

        // row max: quad reduce (this warp's 32 cols), exchange across wn
        float mx_lo = -1e30f, mx_hi = -1e30f;
        #pragma unroll
        for (int nt = 0; nt < 4; nt++) {
            mx_lo = fmaxf(mx_lo, fmaxf(s[nt][0], s[nt][1]));
            mx_hi = fmaxf(mx_hi, fmaxf(s[nt][2], s[nt][3]));
        }
        mx_lo = fmaxf(mx_lo, __shfl_xor_sync(0xffffffffu, mx_lo, 1));
        mx_lo = fmaxf(mx_lo, __shfl_xor_sync(0xffffffffu, mx_lo, 2));
        mx_hi = fmaxf(mx_hi, __shfl_xor_sync(0xffffffffu, mx_hi, 1));
        mx_hi = fmaxf(mx_hi, __shfl_xor_sync(0xffffffffu, mx_hi, 2));
        if (lr == 0) {
            red_max[wn * 64 + row_lo] = mx_lo;
            red_max[wn * 64 + row_hi] = mx_hi;
        }
        __syncthreads();
        mx_lo = fmaxf(mx_lo, red_max[(1 - wn) * 64 + row_lo]);
        mx_hi = fmaxf(mx_hi, red_max[(1 - wn) * 64 + row_hi]);

        float mn_lo = fmaxf(m_lo, mx_lo);
        float mn_hi = fmaxf(m_hi, mx_hi);
        float cr_lo = __expf(m_lo - mn_lo);
        float cr_hi = __expf(m_hi - mn_hi);
        m_lo = mn_lo; m_hi = mn_hi;

        // exp, partial sums, store P (tf32) to smem
        float rs_lo = 0.f, rs_hi = 0.f;
        #pragma unroll
        for (int nt = 0; nt < 4; nt++) {
            float p0 = __expf(s[nt][0] - mn_lo);
            float p1 = __expf(s[nt][1] - mn_lo);
            float p2 = __expf(s[nt][2] - mn_hi);
            float p3 = __expf(s[nt][3] - mn_hi);
            rs_lo += p0 + p1;
            rs_hi += p2 + p3;
            int colb = wn * 32 + nt * 8 + 2 * lr;
            *(uint2*)&Ps[row_lo * VST + colb] = make_uint2(f2tf(p0), f2tf(p1));
            *(uint2*)&Ps[row_hi * VST + colb] = make_uint2(f2tf(p2), f2tf(p3));
        }
        rs_lo += __shfl_xor_sync(0xffffffffu, rs_lo, 1);
        rs_lo += __shfl_xor_sync(0xffffffffu, rs_lo, 2);
        rs_hi += __shfl_xor_sync(0xffffffffu, rs_hi, 1);
        rs_hi += __shfl_xor_sync(0xffffffffu, rs_hi, 2);
        if (lr == 0) {
            red_sum[wn * 64 + row_lo] = rs_lo;
            red_sum[wn * 64 + row_hi] = rs_hi;
        }
        __syncthreads();
        rs_lo += red_sum[(1 - wn) * 64 + row_lo];
        rs_hi += red_sum[(1 - wn) * 64 + row_hi];
        l_lo = l_lo * cr_lo + rs_lo;
        l_hi = l_hi * cr_hi + rs_hi;

        // rescale O accumulators
        #pragma unroll
        for (int nt = 0; nt < 4; nt++) {
            accO[nt][0] *= cr_lo; accO[nt][1] *= cr_lo;
            accO[nt][2] *= cr_hi; accO[nt][3] *= cr_hi;
        }

        // O += P * V  (M=64 i, N=64 d, K=64 j)
        #pragma unroll
        for (int ks = 0; ks < 8; ks++) {
            int jj = ks * 8 + lr;
            uint32_t a0 = Ps[row_lo * VST + jj];
            uint32_t a1 = Ps[row_hi * VST + jj];
            uint32_t a2 = Ps[row_lo * VST + jj + 4];
            uint32_t a3 = Ps[row_hi * VST + jj + 4];
            #pragma unroll
            for (int nt = 0; nt < 4; nt++) {
                int dc = wn * 32 + nt * 8 + lq;
                uint32_t b0 = Vs[dc * VST + jj];
                uint32_t b1 = Vs[dc * VST + jj + 4];
                mma8(accO[nt], a0, a1, a2, a3, b0, b1);
            }
        }
        __syncthreads();   // before next tile's KR/V overwrite
    }

    // write O / l :  out[b, h*64+d, i0+row]
    float inv_lo = 1.f / l_lo;
    float inv_hi = 1.f / l_hi;
    float* ob = out + ((long)b * 256 + h * 64) * HW + i0;
    #pragma unroll
    for (int nt = 0; nt < 4; nt++) {
        int d = wn * 32 + nt * 8 + 2 * lr;
        ob[(long)d * HW + row_lo]       = accO[nt][0] * inv_lo;
        ob[(long)(d + 1) * HW + row_lo] = accO[nt][1] * inv_lo;
        ob[(long)d * HW + row_hi]       = accO[nt][2] * inv_hi;
        ob[(long)(d + 1) * HW + row_hi] = accO[nt][3] * inv_hi;
    }
}

// ---------------------------------------------------------------------------
extern "C" void kernel_launch(void* const* d_in, const int* in_sizes, int n_in,
                              void* d_out, int out_size)
{
    const float* x        = (const float*)d_in[0];
    const float* cv1_w    = (const float*)d_in[1];
    const float* cv1_bn   = (const float*)d_in[2];
    const float* cv2_w    = (const float*)d_in[3];
    const float* cv2_bn   = (const float*)d_in[4];
    const float* m_cv1_w  = (const float*)d_in[5];
    const float* m_cv1_bn = (const float*)d_in[6];
    const float* m_qkv_w  = (const float*)d_in[7];
    const float* m_rw     = (const float*)d_in[8];
    const float* m_rh     = (const float*)d_in[9];
    const float* m_cv2_w  = (const float*)d_in[10];
    const float* m_cv2_bn = (const float*)d_in[11];
    float* out = (float*)d_out;

    float *cat, *z, *qkv, *att, *w3;
    cudaGetSymbolAddress((void**)&cat, g_cat);
    cudaGetSymbolAddress((void**)&z,   g_z);
    cudaGetSymbolAddress((void**)&qkv, g_qkv);
    cudaGetSymbolAddress((void**)&att, g_att);
    cudaGetSymbolAddress((void**)&w3,  g_w3);

    const int FA_SMEM = FA_TOT * 4;   // bytes
    cudaFuncSetAttribute(flash_tf32_kernel,
                         cudaFuncAttributeMaxDynamicSharedMemorySize, FA_SMEM);

    const long CAT_S = 1024L * HW;

    reorder_w3_kernel<<<(2 * 9 * 65536 + 255) / 256, 256>>>(m_cv1_w, w3);

    // cv1: x (512) -> cat[0:512)
    gemm_tf32_kernel<<<dim3(8, 4, BATCH), 256>>>(
        x, cv1_w, cv1_bn, nullptr, cat,
        512, 512, 512L * HW, CAT_S, 0, 3);

    for (int i = 0; i < 2; i++) {
        const float* yin = cat + (long)(256 + i * 256) * HW;

        conv3_tf32_kernel<<<dim3(8, 2, BATCH), 256>>>(
            yin, w3 + (long)i * 9 * 65536, m_cv1_bn + i * 4 * 256,
            z, CAT_S, 256L * HW);

        gemm_tf32_kernel<<<dim3(8, 6, BATCH), 256>>>(
            z, m_qkv_w + (long)i * 768 * 256, nullptr, nullptr, qkv,
            256, 768, 256L * HW, 768L * HW, 0, 0);

        flash_tf32_kernel<<<dim3(16, 4, BATCH), 256, FA_SMEM>>>(
            qkv, m_rw + i * 8192, m_rh + i * 8192, att);

        gemm_tf32_kernel<<<dim3(8, 2, BATCH), 256>>>(
            att, m_cv2_w + (long)i * 256 * 256, m_cv2_bn + i * 4 * 256,
            yin, cat + (long)(512 + i * 256) * HW,
            256, 256, 256L * HW, CAT_S, CAT_S, 7);
    }

    // cv2: cat (1024) -> out (512)
    gemm_tf32_kernel<<<dim3(8, 4, BATCH), 256>>>(
        cat, cv2_w, cv2_bn, nullptr, out,
        1024, 512, CAT_S, 512L * HW, 0, 3);
}

// round 5
// speedup vs baseline: 2.8917x; 1.0159x over previous
#include <cuda_runtime.h>
#include <cstdint>

#define HW 1024
#define BATCH 8

__device__ float g_cat[BATCH * 1024 * HW];
__device__ float g_z  [BATCH * 256  * HW];
__device__ float g_qkv[BATCH * 768  * HW];
__device__ float g_att[BATCH * 256  * HW];
__device__ float g_w3 [2 * 9 * 256 * 256];   // [i][t][co][ci]

// ---------------------------------------------------------------------------
__device__ __forceinline__ uint32_t f2tf(float x) {
    uint32_t r;
    asm("cvt.rna.tf32.f32 %0, %1;" : "=r"(r) : "f"(x));
    return r;
}

__device__ __forceinline__ void mma8(float c[4],
    uint32_t a0, uint32_t a1, uint32_t a2, uint32_t a3,
    uint32_t b0, uint32_t b1)
{
    asm volatile(
        "mma.sync.aligned.m16n8k8.row.col.f32.tf32.tf32.f32 "
        "{%0,%1,%2,%3}, {%4,%5,%6,%7}, {%8,%9}, {%0,%1,%2,%3};"
        : "+f"(c[0]), "+f"(c[1]), "+f"(c[2]), "+f"(c[3])
        : "r"(a0), "r"(a1), "r"(a2), "r"(a3), "r"(b0), "r"(b1));
}

__device__ __forceinline__ void cpa16(void* dst_smem, const void* src) {
    uint32_t d = (uint32_t)__cvta_generic_to_shared(dst_smem);
    asm volatile("cp.async.cg.shared.global [%0], [%1], 16;" :: "r"(d), "l"(src));
}
__device__ __forceinline__ void cp_commit() {
    asm volatile("cp.async.commit_group;");
}
__device__ __forceinline__ void cp_wait1() {
    asm volatile("cp.async.wait_group 1;");
}
__device__ __forceinline__ void cp_wait0() {
    asm volatile("cp.async.wait_group 0;");
}

#define AST 36    // A smem row stride (words)
#define BST 136   // B smem row stride (words)
#define A_WORDS (128 * AST)   // 4608
#define B_WORDS (32 * BST)    // 4352
#define PIPE_SMEM ((2 * A_WORDS + 2 * B_WORDS) * 4)   // 71680 B

// ---------------------------------------------------------------------------
__global__ void reorder_w3_kernel(const float* __restrict__ w, float* __restrict__ o)
{
    int idx = blockIdx.x * 256 + threadIdx.x;
    if (idx >= 2 * 9 * 65536) return;
    int i  = idx / (9 * 65536);
    int r  = idx % (9 * 65536);
    int t  = r / 65536;
    int rc = r % 65536;
    int co = rc >> 8, ci = rc & 255;
    o[idx] = w[((long)(i * 256 + co) * 256 + ci) * 9 + t];
}

// ---------------------------------------------------------------------------
// Shared compute step: one 32-deep K chunk from raw-float smem tiles.
// ---------------------------------------------------------------------------
__device__ __forceinline__ void mma_chunk(
    const float* __restrict__ AF, const float* __restrict__ BF,
    int wm, int wn, int lane, float acc[4][4][4])
{
    #pragma unroll
    for (int ks = 0; ks < 4; ks++) {
        uint32_t a[4][4], bb[4][2];
        int ar = wm * 64 + (lane >> 2);
        int ac = ks * 8 + (lane & 3);
        #pragma unroll
        for (int mt = 0; mt < 4; mt++) {
            int r = ar + mt * 16;
            a[mt][0] = f2tf(AF[r * AST + ac]);
            a[mt][1] = f2tf(AF[(r + 8) * AST + ac]);
            a[mt][2] = f2tf(AF[r * AST + ac + 4]);
            a[mt][3] = f2tf(AF[(r + 8) * AST + ac + 4]);
        }
        int br = ks * 8 + (lane & 3);
        int bc = wn * 32 + (lane >> 2);
        #pragma unroll
        for (int nt = 0; nt < 4; nt++) {
            bb[nt][0] = f2tf(BF[br * BST + bc + nt * 8]);
            bb[nt][1] = f2tf(BF[(br + 4) * BST + bc + nt * 8]);
        }
        #pragma unroll
        for (int mt = 0; mt < 4; mt++)
            #pragma unroll
            for (int nt = 0; nt < 4; nt++)
                mma8(acc[mt][nt], a[mt][0], a[mt][1], a[mt][2], a[mt][3],
                     bb[nt][0], bb[nt][1]);
    }
}

// ---------------------------------------------------------------------------
// Pipelined tf32 GEMM for 1x1 convs. Block 128x128, K-chunk 32, double-buffer
// smem fed by cp.async. flags: 1=BN, 2=SiLU, 4=residual.
// ---------------------------------------------------------------------------
extern __shared__ float pipe_sm[];

__global__ __launch_bounds__(256, 2) void gemm_tf32_kernel(
    const float* __restrict__ X, const float* __restrict__ W,
    const float* __restrict__ bn, const float* __restrict__ res,
    float* __restrict__ out,
    int Cin, int Cout, long xbS, long obS, long rbS, int flags)
{
    float* Af[2] = {pipe_sm, pipe_sm + A_WORDS};
    float* Bf[2] = {pipe_sm + 2 * A_WORDS, pipe_sm + 2 * A_WORDS + B_WORDS};

    const int b   = blockIdx.z;
    const int p0  = blockIdx.x * 128;
    const int co0 = blockIdx.y * 128;
    const int tid = threadIdx.x;
    const int lane = tid & 31, wid = tid >> 5;
    const int wm = wid >> 2, wn = wid & 3;

    const float* Xb = X + (long)b * xbS;

    const int ar_ld = tid >> 3;          // 0..31
    const int ac_ld = (tid & 7) * 4;     // 0..28
    const int bk_ld = tid >> 5;          // 0..7
    const int bp_ld = lane * 4;          // 0..124

    float acc[4][4][4];
    #pragma unroll
    for (int mt = 0; mt < 4; mt++)
        #pragma unroll
        for (int nt = 0; nt < 4; nt++)
            #pragma unroll
            for (int e = 0; e < 4; e++) acc[mt][nt][e] = 0.f;

    // issue chunk 0
    #pragma unroll
    for (int it = 0; it < 4; it++) {
        int r = ar_ld + it * 32;
        cpa16(&Af[0][r * AST + ac_ld], &W[(long)(co0 + r) * Cin + ac_ld]);
    }
    #pragma unroll
    for (int it = 0; it < 4; it++) {
        int kk = bk_ld + it * 8;
        cpa16(&Bf[0][kk * BST + bp_ld], &Xb[(long)kk * HW + p0 + bp_ld]);
    }
    cp_commit();

    int buf = 0;
    for (int k0 = 0; k0 < Cin; k0 += 32) {
        bool next = (k0 + 32 < Cin);
        if (next) {
            int kn = k0 + 32;
            #pragma unroll
            for (int it = 0; it < 4; it++) {
                int r = ar_ld + it * 32;
                cpa16(&Af[buf ^ 1][r * AST + ac_ld],
                      &W[(long)(co0 + r) * Cin + kn + ac_ld]);
            }
            #pragma unroll
            for (int it = 0; it < 4; it++) {
                int kk = bk_ld + it * 8;
                cpa16(&Bf[buf ^ 1][kk * BST + bp_ld],
                      &Xb[(long)(kn + kk) * HW + p0 + bp_ld]);
            }
            cp_commit();
            cp_wait1();
        } else {
            cp_wait0();
        }
        __syncthreads();
        mma_chunk(Af[buf], Bf[buf], wm, wn, lane, acc);
        __syncthreads();
        buf ^= 1;
    }

    // epilogue
    #pragma unroll
    for (int mt = 0; mt < 4; mt++) {
        int r0 = co0 + wm * 64 + mt * 16 + (lane >> 2);
        int r1 = r0 + 8;
        float s0 = 1.f, c0 = 0.f, s1 = 1.f, c1 = 0.f;
        if (flags & 1) {
            float g0 = bn[r0], b0v = bn[Cout + r0], m0 = bn[2*Cout + r0], v0 = bn[3*Cout + r0];
            s0 = g0 * rsqrtf(v0 + 1e-3f); c0 = b0v - m0 * s0;
            float g1 = bn[r1], b1v = bn[Cout + r1], m1 = bn[2*Cout + r1], v1 = bn[3*Cout + r1];
            s1 = g1 * rsqrtf(v1 + 1e-3f); c1 = b1v - m1 * s1;
        }
        #pragma unroll
        for (int nt = 0; nt < 4; nt++) {
            int col = p0 + wn * 32 + nt * 8 + 2 * (lane & 3);
            float v00 = acc[mt][nt][0] * s0 + c0;
            float v01 = acc[mt][nt][1] * s0 + c0;
            float v10 = acc[mt][nt][2] * s1 + c1;
            float v11 = acc[mt][nt][3] * s1 + c1;
            if (flags & 2) {
                v00 = v00 / (1.f + __expf(-v00));
                v01 = v01 / (1.f + __expf(-v01));
                v10 = v10 / (1.f + __expf(-v10));
                v11 = v11 / (1.f + __expf(-v11));
            }
            if (flags & 4) {
                const float* rb = res + (long)b * rbS;
                v00 += rb[(long)r0 * HW + col];
                v01 += rb[(long)r0 * HW + col + 1];
                v10 += rb[(long)r1 * HW + col];
                v11 += rb[(long)r1 * HW + col + 1];
            }
            float* ob = out + (long)b * obS;
            *(float2*)&ob[(long)r0 * HW + col] = make_float2(v00, v01);
            *(float2*)&ob[(long)r1 * HW + col] = make_float2(v10, v11);
        }
    }
}

// ---------------------------------------------------------------------------
// Pipelined tf32 3x3 conv: A via cp.async double buffer, B via register
// prefetch (boundary-predicated), 72 chunks = 9 taps x 8 k-chunks.
// ---------------------------------------------------------------------------
__global__ __launch_bounds__(256, 1) void conv3_tf32_kernel(
    const float* __restrict__ X, const float* __restrict__ Wt,
    const float* __restrict__ bn, float* __restrict__ out,
    long xbS, long obS)
{
    float* Af[2] = {pipe_sm, pipe_sm + A_WORDS};
    float* Bf[2] = {pipe_sm + 2 * A_WORDS, pipe_sm + 2 * A_WORDS + B_WORDS};

    const int b   = blockIdx.z;
    const int p0  = blockIdx.x * 128;
    const int co0 = blockIdx.y * 128;
    const int tid = threadIdx.x;
    const int lane = tid & 31, wid = tid >> 5;
    const int wm = wid >> 2, wn = wid & 3;

    const float* Xb = X + (long)b * xbS;

    const int ar_ld = tid >> 3;
    const int ac_ld = (tid & 7) * 4;

    float acc[4][4][4];
    #pragma unroll
    for (int mt = 0; mt < 4; mt++)
        #pragma unroll
        for (int nt = 0; nt < 4; nt++)
            #pragma unroll
            for (int e = 0; e < 4; e++) acc[mt][nt][e] = 0.f;

    // B prefetch: element e = tid + it*256 -> (kk = e>>7, p = e&127)
    const int pk_base = tid >> 7;        // kk = pk_base + it*2
    const int pp      = tid & 127;
    const int prow    = (p0 + pp) >> 5;
    const int pcol    = (p0 + pp) & 31;

    float bpre[16];

    auto issueA = [&](int c, int bf) {
        int t = c / 8, kc = (c & 7) * 32;
        const float* Wtt = Wt + t * 65536;
        #pragma unroll
        for (int it = 0; it < 4; it++) {
            int r = ar_ld + it * 32;
            cpa16(&Af[bf][r * AST + ac_ld],
                  &Wtt[(long)(co0 + r) * 256 + kc + ac_ld]);
        }
    };
    auto loadB = [&](int c, float* v) {
        int t = c / 8, kc = (c & 7) * 32;
        int dy = t / 3 - 1, dx = t % 3 - 1;
        int row = prow + dy, col = pcol + dx;
        bool ok = ((unsigned)row < 32u) && ((unsigned)col < 32u);
        const float* base = Xb + (long)kc * HW + row * 32 + col;
        #pragma unroll
        for (int it = 0; it < 16; it++)
            v[it] = ok ? base[(long)(pk_base + it * 2) * HW] : 0.f;
    };
    auto storeB = [&](const float* v, int bf) {
        #pragma unroll
        for (int it = 0; it < 16; it++)
            Bf[bf][(pk_base + it * 2) * BST + pp] = v[it];
    };

    loadB(0, bpre);
    issueA(0, 0);
    cp_commit();
    storeB(bpre, 0);

    int buf = 0;
    for (int c = 0; c < 72; c++) {
        bool next = (c + 1 < 72);
        if (next) {
            issueA(c + 1, buf ^ 1);
            cp_commit();
            loadB(c + 1, bpre);       // long-latency; lands during compute
            cp_wait1();
        } else {
            cp_wait0();
        }
        __syncthreads();
        mma_chunk(Af[buf], Bf[buf], wm, wn, lane, acc);
        if (next) storeB(bpre, buf ^ 1);
        __syncthreads();
        buf ^= 1;
    }

    #pragma unroll
    for (int mt = 0; mt < 4; mt++) {
        int r0 = co0 + wm * 64 + mt * 16 + (lane >> 2);
        int r1 = r0 + 8;
        float g0 = bn[r0], b0v = bn[256 + r0], m0 = bn[512 + r0], v0 = bn[768 + r0];
        float s0 = g0 * rsqrtf(v0 + 1e-3f), c0 = b0v - m0 * s0;
        float g1 = bn[r1], b1v = bn[256 + r1], m1 = bn[512 + r1], v1 = bn[768 + r1];
        float s1 = g1 * rsqrtf(v1 + 1e-3f), c1 = b1v - m1 * s1;
        #pragma unroll
        for (int nt = 0; nt < 4; nt++) {
            int col = p0 + wn * 32 + nt * 8 + 2 * (lane & 3);
            float v00 = acc[mt][nt][0] * s0 + c0;
            float v01 = acc[mt][nt][1] * s0 + c0;
            float v10 = acc[mt][nt][2] * s1 + c1;
            float v11 = acc[mt][nt][3] * s1 + c1;
            v00 = v00 / (1.f + __expf(-v00));
            v01 = v01 / (1.f + __expf(-v01));
            v10 = v10 / (1.f + __expf(-v10));
            v11 = v11 / (1.f + __expf(-v11));
            float* ob = out + (long)b * obS;
            *(float2*)&ob[(long)r0 * HW + col] = make_float2(v00, v01);
            *(float2*)&ob[(long)r1 * HW + col] = make_float2(v10, v11);
        }
    }
}

// ---------------------------------------------------------------------------
// tf32 flash attention (unchanged from round 3).
// ---------------------------------------------------------------------------
#define QST 72
#define VST 68
#define FA_Q   0
#define FA_KR  (64 * QST)
#define FA_V   (FA_KR + 64 * QST)
#define FA_P   (FA_V + 64 * VST)
#define FA_RED (FA_P + 64 * VST)
#define FA_TOT (FA_RED + 256)

extern __shared__ uint32_t fa_u[];

__global__ __launch_bounds__(256) void flash_tf32_kernel(
    const float* __restrict__ qkv, const float* __restrict__ rw,
    const float* __restrict__ rh, float* __restrict__ out)
{
    uint32_t* Qs  = fa_u + FA_Q;
    uint32_t* KRs = fa_u + FA_KR;
    uint32_t* Vs  = fa_u + FA_V;
    uint32_t* Ps  = fa_u + FA_P;
    float* red_max = (float*)(fa_u + FA_RED);
    float* red_sum = red_max + 128;

    const int b  = blockIdx.z;
    const int h  = blockIdx.y;
    const int i0 = blockIdx.x * 64;
    const int tid  = threadIdx.x;
    const int lane = tid & 31, wid = tid >> 5;
    const int wm = wid >> 1;
    const int wn = wid & 1;
    const int lq = lane >> 2;
    const int lr = lane & 3;

    const float* qb  = qkv + ((long)b * 768 + h * 64) * HW;
    const float* kb  = qb + 256 * HW;
    const float* vb  = qb + 512 * HW;
    const float* rwh = rw + h * 64 * 32;
    const float* rhh = rh + h * 64 * 32;

    #pragma unroll
    for (int e = tid; e < 4096; e += 256) {
        int d = e >> 6, i = e & 63;
        Qs[d * QST + i] = f2tf(qb[(long)d * HW + i0 + i]);
    }

    const int row_lo = wm * 16 + lq;
    const int row_hi = row_lo + 8;

    float m_lo = -1e30f, m_hi = -1e30f, l_lo = 0.f, l_hi = 0.f;
    float accO[4][4];
    #pragma unroll
    for (int nt = 0; nt < 4; nt++)
        #pragma unroll
        for (int e = 0; e < 4; e++) accO[nt][e] = 0.f;

    __syncthreads();

    for (int j0 = 0; j0 < HW; j0 += 64) {
        #pragma unroll
        for (int e = tid; e < 4096; e += 256) {
            int d = e >> 6, j = e & 63;
            int jj = j0 + j;
            float krv = kb[(long)d * HW + jj]
                      + rwh[d * 32 + (jj & 31)]
                      + rhh[d * 32 + (jj >> 5)];
            KRs[d * QST + j] = f2tf(krv);
            Vs[d * VST + j]  = f2tf(vb[(long)d * HW + jj]);
        }
        __syncthreads();

        float s[4][4];
        #pragma unroll
        for (int nt = 0; nt < 4; nt++)
            #pragma unroll
            for (int e = 0; e < 4; e++) s[nt][e] = 0.f;

        #pragma unroll
        for (int ks = 0; ks < 8; ks++) {
            int d0 = ks * 8 + lr;
            uint32_t a0 = Qs[d0 * QST + row_lo];
            uint32_t a1 = Qs[d0 * QST + row_hi];
            uint32_t a2 = Qs[(d0 + 4) * QST + row_lo];
            uint32_t a3 = Qs[(d0 + 4) * QST + row_hi];
            #pragma unroll
            for (int nt = 0; nt < 4; nt++) {
                int jc = wn * 32 + nt * 8 + lq;
                uint32_t b0 = KRs[d0 * QST + jc];
                uint32_t b1 = KRs[(d0 + 4) * QST + jc];
                mma8(s[nt], a0, a1, a2, a3, b0, b1);
            }
        }

        #pragma unroll
        for (int nt = 0; nt < 4; nt++)
            #pragma unroll
            for (int e = 0; e < 4; e++) s[nt][e] *= 0.125f;

        float mx_lo = -1e30f, mx_hi = -1e30f;
        #pragma unroll
        for (int nt = 0; nt < 4; nt++) {
            mx_lo = fmaxf(mx_lo, fmaxf(s[nt][0], s[nt][1]));
            mx_hi = fmaxf(mx_hi, fmaxf(s[nt][2], s[nt][3]));
        }
        mx_lo = fmaxf(mx_lo, __shfl_xor_sync(0xffffffffu, mx_lo, 1));
        mx_lo = fmaxf(mx_lo, __shfl_xor_sync(0xffffffffu, mx_lo, 2));
        mx_hi = fmaxf(mx_hi, __shfl_xor_sync(0xffffffffu, mx_hi, 1));
        mx_hi = fmaxf(mx_hi, __shfl_xor_sync(0xffffffffu, mx_hi, 2));
        if (lr == 0) {
            red_max[wn * 64 + row_lo] = mx_lo;
            red_max[wn * 64 + row_hi] = mx_hi;
        }
        __syncthreads();
        mx_lo = fmaxf(mx_lo, red_max[(1 - wn) * 64 + row_lo]);
        mx_hi = fmaxf(mx_hi, red_max[(1 - wn) * 64 + row_hi]);

        float mn_lo = fmaxf(m_lo, mx_lo);
        float mn_hi = fmaxf(m_hi, mx_hi);
        float cr_lo = __expf(m_lo - mn_lo);
        float cr_hi = __expf(m_hi - mn_hi);
        m_lo = mn_lo; m_hi = mn_hi;

        float rs_lo = 0.f, rs_hi = 0.f;
        #pragma unroll
        for (int nt = 0; nt < 4; nt++) {
            float p0 = __expf(s[nt][0] - mn_lo);
            float p1 = __expf(s[nt][1] - mn_lo);
            float p2 = __expf(s[nt][2] - mn_hi);
            float p3 = __expf(s[nt][3] - mn_hi);
            rs_lo += p0 + p1;
            rs_hi += p2 + p3;
            int colb = wn * 32 + nt * 8 + 2 * lr;
            *(uint2*)&Ps[row_lo * VST + colb] = make_uint2(f2tf(p0), f2tf(p1));
            *(uint2*)&Ps[row_hi * VST + colb] = make_uint2(f2tf(p2), f2tf(p3));
        }
        rs_lo += __shfl_xor_sync(0xffffffffu, rs_lo, 1);
        rs_lo += __shfl_xor_sync(0xffffffffu, rs_lo, 2);
        rs_hi += __shfl_xor_sync(0xffffffffu, rs_hi, 1);
        rs_hi += __shfl_xor_sync(0xffffffffu, rs_hi, 2);
        if (lr == 0) {
            red_sum[wn * 64 + row_lo] = rs_lo;
            red_sum[wn * 64 + row_hi] = rs_hi;
        }
        __syncthreads();
        rs_lo += red_sum[(1 - wn) * 64 + row_lo];
        rs_hi += red_sum[(1 - wn) * 64 + row_hi];
        l_lo = l_lo * cr_lo + rs_lo;
        l_hi = l_hi * cr_hi + rs_hi;

        #pragma unroll
        for (int nt = 0; nt < 4; nt++) {
            accO[nt][0] *= cr_lo; accO[nt][1] *= cr_lo;
            accO[nt][2] *= cr_hi; accO[nt][3] *= cr_hi;
        }

        #pragma unroll
        for (int ks = 0; ks < 8; ks++) {
            int jj = ks * 8 + lr;
            uint32_t a0 = Ps[row_lo * VST + jj];
            uint32_t a1 = Ps[row_hi * VST + jj];
            uint32_t a2 = Ps[row_lo * VST + jj + 4];
            uint32_t a3 = Ps[row_hi * VST + jj + 4];
            #pragma unroll
            for (int nt = 0; nt < 4; nt++) {
                int dc = wn * 32 + nt * 8 + lq;
                uint32_t b0 = Vs[dc * VST + jj];
                uint32_t b1 = Vs[dc * VST + jj + 4];
                mma8(accO[nt], a0, a1, a2, a3, b0, b1);
            }
        }
        __syncthreads();
    }

    float inv_lo = 1.f / l_lo;
    float inv_hi = 1.f / l_hi;
    float* ob = out + ((long)b * 256 + h * 64) * HW + i0;
    #pragma unroll
    for (int nt = 0; nt < 4; nt++) {
        int d = wn * 32 + nt * 8 + 2 * lr;
        ob[(long)d * HW + row_lo]       = accO[nt][0] * inv_lo;
        ob[(long)(d + 1) * HW + row_lo] = accO[nt][1] * inv_lo;
        ob[(long)d * HW + row_hi]       = accO[nt][2] * inv_hi;
        ob[(long)(d + 1) * HW + row_hi] = accO[nt][3] * inv_hi;
    }
}

// ---------------------------------------------------------------------------
extern "C" void kernel_launch(void* const* d_in, const int* in_sizes, int n_in,
                              void* d_out, int out_size)
{
    const float* x        = (const float*)d_in[0];
    const float* cv1_w    = (const float*)d_in[1];
    const float* cv1_bn   = (const float*)d_in[2];
    const float* cv2_w    = (const float*)d_in[3];
    const float* cv2_bn   = (const float*)d_in[4];
    const float* m_cv1_w  = (const float*)d_in[5];
    const float* m_cv1_bn = (const float*)d_in[6];
    const float* m_qkv_w  = (const float*)d_in[7];
    const float* m_rw     = (const float*)d_in[8];
    const float* m_rh     = (const float*)d_in[9];
    const float* m_cv2_w  = (const float*)d_in[10];
    const float* m_cv2_bn = (const float*)d_in[11];
    float* out = (float*)d_out;

    float *cat, *z, *qkv, *att, *w3;
    cudaGetSymbolAddress((void**)&cat, g_cat);
    cudaGetSymbolAddress((void**)&z,   g_z);
    cudaGetSymbolAddress((void**)&qkv, g_qkv);
    cudaGetSymbolAddress((void**)&att, g_att);
    cudaGetSymbolAddress((void**)&w3,  g_w3);

    const int FA_SMEM = FA_TOT * 4;
    cudaFuncSetAttribute(flash_tf32_kernel,
                         cudaFuncAttributeMaxDynamicSharedMemorySize, FA_SMEM);
    cudaFuncSetAttribute(gemm_tf32_kernel,
                         cudaFuncAttributeMaxDynamicSharedMemorySize, PIPE_SMEM);
    cudaFuncSetAttribute(conv3_tf32_kernel,
                         cudaFuncAttributeMaxDynamicSharedMemorySize, PIPE_SMEM);

    const long CAT_S = 1024L * HW;

    reorder_w3_kernel<<<(2 * 9 * 65536 + 255) / 256, 256>>>(m_cv1_w, w3);

    gemm_tf32_kernel<<<dim3(8, 4, BATCH), 256, PIPE_SMEM>>>(
        x, cv1_w, cv1_bn, nullptr, cat,
        512, 512, 512L * HW, CAT_S, 0, 3);

    for (int i = 0; i < 2; i++) {
        const float* yin = cat + (long)(256 + i * 256) * HW;

        conv3_tf32_kernel<<<dim3(8, 2, BATCH), 256, PIPE_SMEM>>>(
            yin, w3 + (long)i * 9 * 65536, m_cv1_bn + i * 4 * 256,
            z, CAT_S, 256L * HW);

        gemm_tf32_kernel<<<dim3(8, 6, BATCH), 256, PIPE_SMEM>>>(
            z, m_qkv_w + (long)i * 768 * 256, nullptr, nullptr, qkv,
            256, 768, 256L * HW, 768L * HW, 0, 0);

        flash_tf32_kernel<<<dim3(16, 4, BATCH), 256, FA_SMEM>>>(
            qkv, m_rw + i * 8192, m_rh + i * 8192, att);

        gemm_tf32_kernel<<<dim3(8, 2, BATCH), 256, PIPE_SMEM>>>(
            att, m_cv2_w + (long)i * 256 * 256, m_cv2_bn + i * 4 * 256,
            yin, cat + (long)(512 + i * 256) * HW,
            256, 256, 256L * HW, CAT_S, CAT_S, 7);
    }

    gemm_tf32_kernel<<<dim3(8, 4, BATCH), 256, PIPE_SMEM>>>(
        cat, cv2_w, cv2_bn, nullptr, out,
        1024, 512, CAT_S, 512L * HW, 0, 3);
}

// round 8
// speedup vs baseline: 3.0980x; 1.0713x over previous
#include <cuda_runtime.h>
#include <cstdint>

#define HW 1024
#define BATCH 8

__device__ float g_cat [BATCH * 1024 * HW];
__device__ float g_z   [BATCH * 256  * HW];
__device__ float g_qkv [BATCH * 768  * HW];
__device__ float g_att [BATCH * 256  * HW];
__device__ float g_w3  [2 * 9 * 256 * 256];          // [i][t][co][ci]
__device__ float g_part[3 * BATCH * 256 * HW];       // conv3 tap partials

// ---------------------------------------------------------------------------
__device__ __forceinline__ uint32_t f2tf(float x) {
    uint32_t r;
    asm("cvt.rna.tf32.f32 %0, %1;" : "=r"(r) : "f"(x));
    return r;
}

__device__ __forceinline__ void mma8(float c[4],
    uint32_t a0, uint32_t a1, uint32_t a2, uint32_t a3,
    uint32_t b0, uint32_t b1)
{
    asm volatile(
        "mma.sync.aligned.m16n8k8.row.col.f32.tf32.tf32.f32 "
        "{%0,%1,%2,%3}, {%4,%5,%6,%7}, {%8,%9}, {%0,%1,%2,%3};"
        : "+f"(c[0]), "+f"(c[1]), "+f"(c[2]), "+f"(c[3])
        : "r"(a0), "r"(a1), "r"(a2), "r"(a3), "r"(b0), "r"(b1));
}

#define AST 36
#define BST 136

// ---------------------------------------------------------------------------
__global__ void reorder_w3_kernel(const float* __restrict__ w, float* __restrict__ o)
{
    int idx = blockIdx.x * 256 + threadIdx.x;
    if (idx >= 2 * 9 * 65536) return;
    int i  = idx / (9 * 65536);
    int r  = idx % (9 * 65536);
    int t  = r / 65536;
    int rc = r % 65536;
    int co = rc >> 8, ci = rc & 255;
    o[idx] = w[((long)(i * 256 + co) * 256 + ci) * 9 + t];
}

// ---------------------------------------------------------------------------
// One 32-deep K chunk from pre-converted tf32 smem tiles (R3 structure).
// ---------------------------------------------------------------------------
__device__ __forceinline__ void mma_chunk(
    const uint32_t* __restrict__ As, const uint32_t* __restrict__ Bs,
    int wm, int wn, int lane, float acc[4][4][4])
{
    #pragma unroll
    for (int ks = 0; ks < 4; ks++) {
        uint32_t a[4][4], bb[4][2];
        int ar = wm * 64 + (lane >> 2);
        int ac = ks * 8 + (lane & 3);
        #pragma unroll
        for (int mt = 0; mt < 4; mt++) {
            int r = ar + mt * 16;
            a[mt][0] = As[r * AST + ac];
            a[mt][1] = As[(r + 8) * AST + ac];
            a[mt][2] = As[r * AST + ac + 4];
            a[mt][3] = As[(r + 8) * AST + ac + 4];
        }
        int br = ks * 8 + (lane & 3);
        int bc = wn * 32 + (lane >> 2);
        #pragma unroll
        for (int nt = 0; nt < 4; nt++) {
            bb[nt][0] = Bs[br * BST + bc + nt * 8];
            bb[nt][1] = Bs[(br + 4) * BST + bc + nt * 8];
        }
        #pragma unroll
        for (int mt = 0; mt < 4; mt++)
            #pragma unroll
            for (int nt = 0; nt < 4; nt++)
                mma8(acc[mt][nt], a[mt][0], a[mt][1], a[mt][2], a[mt][3],
                     bb[nt][0], bb[nt][1]);
    }
}

// ---------------------------------------------------------------------------
// tf32 GEMM for 1x1 convs (R3 structure: convert at store, synchronous).
// Block 128(co) x 128(px), K-chunk 32. flags: 1=BN, 2=SiLU, 4=residual.
// ---------------------------------------------------------------------------
__global__ __launch_bounds__(256) void gemm_tf32_kernel(
    const float* __restrict__ X, const float* __restrict__ W,
    const float* __restrict__ bn, const float* __restrict__ res,
    float* __restrict__ out,
    int Cin, int Cout, long xbS, long obS, long rbS, int flags)
{
    __shared__ uint32_t As[128 * AST];
    __shared__ uint32_t Bs[32 * BST];

    const int b   = blockIdx.z;
    const int p0  = blockIdx.x * 128;
    const int co0 = blockIdx.y * 128;
    const int tid = threadIdx.x;
    const int lane = tid & 31, wid = tid >> 5;
    const int wm = wid >> 2, wn = wid & 3;

    const float* Xb = X + (long)b * xbS;

    float acc[4][4][4];
    #pragma unroll
    for (int mt = 0; mt < 4; mt++)
        #pragma unroll
        for (int nt = 0; nt < 4; nt++)
            #pragma unroll
            for (int e = 0; e < 4; e++) acc[mt][nt][e] = 0.f;

    for (int k0 = 0; k0 < Cin; k0 += 32) {
        #pragma unroll
        for (int it = 0; it < 4; it++) {
            int r = (tid >> 3) + it * 32;
            int c = (tid & 7) * 4;
            float4 v = *(const float4*)&W[(long)(co0 + r) * Cin + k0 + c];
            As[r * AST + c + 0] = f2tf(v.x);
            As[r * AST + c + 1] = f2tf(v.y);
            As[r * AST + c + 2] = f2tf(v.z);
            As[r * AST + c + 3] = f2tf(v.w);
        }
        #pragma unroll
        for (int it = 0; it < 4; it++) {
            int kk = (tid >> 5) + it * 8;
            int pp = lane * 4;
            float4 v = *(const float4*)&Xb[(long)(k0 + kk) * HW + p0 + pp];
            Bs[kk * BST + pp + 0] = f2tf(v.x);
            Bs[kk * BST + pp + 1] = f2tf(v.y);
            Bs[kk * BST + pp + 2] = f2tf(v.z);
            Bs[kk * BST + pp + 3] = f2tf(v.w);
        }
        __syncthreads();
        mma_chunk(As, Bs, wm, wn, lane, acc);
        __syncthreads();
    }

    #pragma unroll
    for (int mt = 0; mt < 4; mt++) {
        int r0 = co0 + wm * 64 + mt * 16 + (lane >> 2);
        int r1 = r0 + 8;
        float s0 = 1.f, c0 = 0.f, s1 = 1.f, c1 = 0.f;
        if (flags & 1) {
            float g0 = bn[r0], b0v = bn[Cout + r0], m0 = bn[2*Cout + r0], v0 = bn[3*Cout + r0];
            s0 = g0 * rsqrtf(v0 + 1e-3f); c0 = b0v - m0 * s0;
            float g1 = bn[r1], b1v = bn[Cout + r1], m1 = bn[2*Cout + r1], v1 = bn[3*Cout + r1];
            s1 = g1 * rsqrtf(v1 + 1e-3f); c1 = b1v - m1 * s1;
        }
        #pragma unroll
        for (int nt = 0; nt < 4; nt++) {
            int col = p0 + wn * 32 + nt * 8 + 2 * (lane & 3);
            float v00 = acc[mt][nt][0] * s0 + c0;
            float v01 = acc[mt][nt][1] * s0 + c0;
            float v10 = acc[mt][nt][2] * s1 + c1;
            float v11 = acc[mt][nt][3] * s1 + c1;
            if (flags & 2) {
                v00 = v00 / (1.f + __expf(-v00));
                v01 = v01 / (1.f + __expf(-v01));
                v10 = v10 / (1.f + __expf(-v10));
                v11 = v11 / (1.f + __expf(-v11));
            }
            if (flags & 4) {
                const float* rb = res + (long)b * rbS;
                v00 += rb[(long)r0 * HW + col];
                v01 += rb[(long)r0 * HW + col + 1];
                v10 += rb[(long)r1 * HW + col];
                v11 += rb[(long)r1 * HW + col + 1];
            }
            float* ob = out + (long)b * obS;
            *(float2*)&ob[(long)r0 * HW + col] = make_float2(v00, v01);
            *(float2*)&ob[(long)r1 * HW + col] = make_float2(v10, v11);
        }
    }
}

// ---------------------------------------------------------------------------
// Tap-split tf32 3x3 conv: each block computes 3 of the 9 taps (K-depth 768)
// and writes a raw fp32 partial. grid (8, 2*3, BATCH) = 384 blocks.
// Partials layout: g_part[part][b][co][p].
// ---------------------------------------------------------------------------
__global__ __launch_bounds__(256) void conv3_part_kernel(
    const float* __restrict__ X, const float* __restrict__ Wt,
    float* __restrict__ part_out, long xbS)
{
    __shared__ uint32_t As[128 * AST];
    __shared__ uint32_t Bs[32 * BST];

    const int b    = blockIdx.z;
    const int p0   = blockIdx.x * 128;
    const int part = blockIdx.y >> 1;
    const int co0  = (blockIdx.y & 1) * 128;
    const int tid  = threadIdx.x;
    const int lane = tid & 31, wid = tid >> 5;
    const int wm = wid >> 2, wn = wid & 3;

    const float* Xb = X + (long)b * xbS;

    float acc[4][4][4];
    #pragma unroll
    for (int mt = 0; mt < 4; mt++)
        #pragma unroll
        for (int nt = 0; nt < 4; nt++)
            #pragma unroll
            for (int e = 0; e < 4; e++) acc[mt][nt][e] = 0.f;

    for (int c = 0; c < 24; c++) {
        const int t  = part * 3 + (c >> 3);
        const int kc = (c & 7) * 32;
        const int dy = t / 3 - 1, dx = t % 3 - 1;
        const float* Wtt = Wt + t * 65536;

        #pragma unroll
        for (int it = 0; it < 4; it++) {
            int r = (tid >> 3) + it * 32;
            int cc = (tid & 7) * 4;
            float4 v = *(const float4*)&Wtt[(long)(co0 + r) * 256 + kc + cc];
            As[r * AST + cc + 0] = f2tf(v.x);
            As[r * AST + cc + 1] = f2tf(v.y);
            As[r * AST + cc + 2] = f2tf(v.z);
            As[r * AST + cc + 3] = f2tf(v.w);
        }
        #pragma unroll
        for (int e = tid; e < 4096; e += 256) {
            int kk = e >> 7, p = e & 127;
            int pix = p0 + p;
            int row = (pix >> 5) + dy;
            int col = (pix & 31) + dx;
            float xv = 0.f;
            if ((unsigned)row < 32u && (unsigned)col < 32u)
                xv = Xb[(long)(kc + kk) * HW + row * 32 + col];
            Bs[kk * BST + p] = f2tf(xv);
        }
        __syncthreads();
        mma_chunk(As, Bs, wm, wn, lane, acc);
        __syncthreads();
    }

    float* ob = part_out + ((long)part * BATCH + b) * 256 * HW;
    #pragma unroll
    for (int mt = 0; mt < 4; mt++) {
        int r0 = co0 + wm * 64 + mt * 16 + (lane >> 2);
        int r1 = r0 + 8;
        #pragma unroll
        for (int nt = 0; nt < 4; nt++) {
            int col = p0 + wn * 32 + nt * 8 + 2 * (lane & 3);
            *(float2*)&ob[(long)r0 * HW + col] =
                make_float2(acc[mt][nt][0], acc[mt][nt][1]);
            *(float2*)&ob[(long)r1 * HW + col] =
                make_float2(acc[mt][nt][2], acc[mt][nt][3]);
        }
    }
}

// ---------------------------------------------------------------------------
// Reduce 3 tap partials + BN + SiLU -> g_z.  Vectorized float4.
// ---------------------------------------------------------------------------
__global__ void tap_reduce_kernel(const float* __restrict__ part,
                                  const float* __restrict__ bn,
                                  float* __restrict__ out)
{
    const long PS = (long)BATCH * 256 * HW;
    long idx = (long)blockIdx.x * 256 + threadIdx.x;   // float4 index
    if (idx >= PS / 4) return;
    long e = idx * 4;
    int ch = (int)((e / HW) & 255);

    float4 a = *(const float4*)&part[e];
    float4 b4 = *(const float4*)&part[PS + e];
    float4 c4 = *(const float4*)&part[2 * PS + e];

    float g = bn[ch], bb = bn[256 + ch], mu = bn[512 + ch], vv = bn[768 + ch];
    float s = g * rsqrtf(vv + 1e-3f);
    float c = bb - mu * s;

    float v[4] = {a.x + b4.x + c4.x, a.y + b4.y + c4.y,
                  a.z + b4.z + c4.z, a.w + b4.w + c4.w};
    #pragma unroll
    for (int i = 0; i < 4; i++) {
        float t = v[i] * s + c;
        v[i] = t / (1.f + __expf(-t));
    }
    *(float4*)&out[e] = make_float4(v[0], v[1], v[2], v[3]);
}

// ---------------------------------------------------------------------------
// tf32 flash attention (unchanged).
// ---------------------------------------------------------------------------
#define QST 72
#define VST 68
#define FA_Q   0
#define FA_KR  (64 * QST)
#define FA_V   (FA_KR + 64 * QST)
#define FA_P   (FA_V + 64 * VST)
#define FA_RED (FA_P + 64 * VST)
#define FA_TOT (FA_RED + 256)

extern __shared__ uint32_t fa_u[];

__global__ __launch_bounds__(256) void flash_tf32_kernel(
    const float* __restrict__ qkv, const float* __restrict__ rw,
    const float* __restrict__ rh, float* __restrict__ out)
{
    uint32_t* Qs  = fa_u + FA_Q;
    uint32_t* KRs = fa_u + FA_KR;
    uint32_t* Vs  = fa_u + FA_V;
    uint32_t* Ps  = fa_u + FA_P;
    float* red_max = (float*)(fa_u + FA_RED);
    float* red_sum = red_max + 128;

    const int b  = blockIdx.z;
    const int h  = blockIdx.y;
    const int i0 = blockIdx.x * 64;
    const int tid  = threadIdx.x;
    const int lane = tid & 31, wid = tid >> 5;
    const int wm = wid >> 1;
    const int wn = wid & 1;
    const int lq = lane >> 2;
    const int lr = lane & 3;

    const float* qb  = qkv + ((long)b * 768 + h * 64) * HW;
    const float* kb  = qb + 256 * HW;
    const float* vb  = qb + 512 * HW;
    const float* rwh = rw + h * 64 * 32;
    const float* rhh = rh + h * 64 * 32;

    #pragma unroll
    for (int e = tid; e < 4096; e += 256) {
        int d = e >> 6, i = e & 63;
        Qs[d * QST + i] = f2tf(qb[(long)d * HW + i0 + i]);
    }

    const int row_lo = wm * 16 + lq;
    const int row_hi = row_lo + 8;

    float m_lo = -1e30f, m_hi = -1e30f, l_lo = 0.f, l_hi = 0.f;
    float accO[4][4];
    #pragma unroll
    for (int nt = 0; nt < 4; nt++)
        #pragma unroll
        for (int e = 0; e < 4; e++) accO[nt][e] = 0.f;

    __syncthreads();

    for (int j0 = 0; j0 < HW; j0 += 64) {
        #pragma unroll
        for (int e = tid; e < 4096; e += 256) {
            int d = e >> 6, j = e & 63;
            int jj = j0 + j;
            float krv = kb[(long)d * HW + jj]
                      + rwh[d * 32 + (jj & 31)]
                      + rhh[d * 32 + (jj >> 5)];
            KRs[d * QST + j] = f2tf(krv);
            Vs[d * VST + j]  = f2tf(vb[(long)d * HW + jj]);
        }
        __syncthreads();

        float s[4][4];
        #pragma unroll
        for (int nt = 0; nt < 4; nt++)
            #pragma unroll
            for (int e = 0; e < 4; e++) s[nt][e] = 0.f;

        #pragma unroll
        for (int ks = 0; ks < 8; ks++) {
            int d0 = ks * 8 + lr;
            uint32_t a0 = Qs[d0 * QST + row_lo];
            uint32_t a1 = Qs[d0 * QST + row_hi];
            uint32_t a2 = Qs[(d0 + 4) * QST + row_lo];
            uint32_t a3 = Qs[(d0 + 4) * QST + row_hi];
            #pragma unroll
            for (int nt = 0; nt < 4; nt++) {
                int jc = wn * 32 + nt * 8 + lq;
                uint32_t b0 = KRs[d0 * QST + jc];
                uint32_t b1 = KRs[(d0 + 4) * QST + jc];
                mma8(s[nt], a0, a1, a2, a3, b0, b1);
            }
        }

        #pragma unroll
        for (int nt = 0; nt < 4; nt++)
            #pragma unroll
            for (int e = 0; e < 4; e++) s[nt][e] *= 0.125f;

        float mx_lo = -1e30f, mx_hi = -1e30f;
        #pragma unroll
        for (int nt = 0; nt < 4; nt++) {
            mx_lo = fmaxf(mx_lo, fmaxf(s[nt][0], s[nt][1]));
            mx_hi = fmaxf(mx_hi, fmaxf(s[nt][2], s[nt][3]));
        }
        mx_lo = fmaxf(mx_lo, __shfl_xor_sync(0xffffffffu, mx_lo, 1));
        mx_lo = fmaxf(mx_lo, __shfl_xor_sync(0xffffffffu, mx_lo, 2));
        mx_hi = fmaxf(mx_hi, __shfl_xor_sync(0xffffffffu, mx_hi, 1));
        mx_hi = fmaxf(mx_hi, __shfl_xor_sync(0xffffffffu, mx_hi, 2));
        if (lr == 0) {
            red_max[wn * 64 + row_lo] = mx_lo;
            red_max[wn * 64 + row_hi] = mx_hi;
        }
        __syncthreads();
        mx_lo = fmaxf(mx_lo, red_max[(1 - wn) * 64 + row_lo]);
        mx_hi = fmaxf(mx_hi, red_max[(1 - wn) * 64 + row_hi]);

        float mn_lo = fmaxf(m_lo, mx_lo);
        float mn_hi = fmaxf(m_hi, mx_hi);
        float cr_lo = __expf(m_lo - mn_lo);
        float cr_hi = __expf(m_hi - mn_hi);
        m_lo = mn_lo; m_hi = mn_hi;

        float rs_lo = 0.f, rs_hi = 0.f;
        #pragma unroll
        for (int nt = 0; nt < 4; nt++) {
            float p0 = __expf(s[nt][0] - mn_lo);
            float p1 = __expf(s[nt][1] - mn_lo);
            float p2 = __expf(s[nt][2] - mn_hi);
            float p3 = __expf(s[nt][3] - mn_hi);
            rs_lo += p0 + p1;
            rs_hi += p2 + p3;
            int colb = wn * 32 + nt * 8 + 2 * lr;
            *(uint2*)&Ps[row_lo * VST + colb] = make_uint2(f2tf(p0), f2tf(p1));
            *(uint2*)&Ps[row_hi * VST + colb] = make_uint2(f2tf(p2), f2tf(p3));
        }
        rs_lo += __shfl_xor_sync(0xffffffffu, rs_lo, 1);
        rs_lo += __shfl_xor_sync(0xffffffffu, rs_lo, 2);
        rs_hi += __shfl_xor_sync(0xffffffffu, rs_hi, 1);
        rs_hi += __shfl_xor_sync(0xffffffffu, rs_hi, 2);
        if (lr == 0) {
            red_sum[wn * 64 + row_lo] = rs_lo;
            red_sum[wn * 64 + row_hi] = rs_hi;
        }
        __syncthreads();
        rs_lo += red_sum[(1 - wn) * 64 + row_lo];
        rs_hi += red_sum[(1 - wn) * 64 + row_hi];
        l_lo = l_lo * cr_lo + rs_lo;
        l_hi = l_hi * cr_hi + rs_hi;

        #pragma unroll
        for (int nt = 0; nt < 4; nt++) {
            accO[nt][0] *= cr_lo; accO[nt][1] *= cr_lo;
            accO[nt][2] *= cr_hi; accO[nt][3] *= cr_hi;
        }

        #pragma unroll
        for (int ks = 0; ks < 8; ks++) {
            int jj = ks * 8 + lr;
            uint32_t a0 = Ps[row_lo * VST + jj];
            uint32_t a1 = Ps[row_hi * VST + jj];
            uint32_t a2 = Ps[row_lo * VST + jj + 4];
            uint32_t a3 = Ps[row_hi * VST + jj + 4];
            #pragma unroll
            for (int nt = 0; nt < 4; nt++) {
                int dc = wn * 32 + nt * 8 + lq;
                uint32_t b0 = Vs[dc * VST + jj];
                uint32_t b1 = Vs[dc * VST + jj + 4];
                mma8(accO[nt], a0, a1, a2, a3, b0, b1);
            }
        }
        __syncthreads();
    }

    float inv_lo = 1.f / l_lo;
    float inv_hi = 1.f / l_hi;
    float* ob = out + ((long)b * 256 + h * 64) * HW + i0;
    #pragma unroll
    for (int nt = 0; nt < 4; nt++) {
        int d = wn * 32 + nt * 8 + 2 * lr;
        ob[(long)d * HW + row_lo]       = accO[nt][0] * inv_lo;
        ob[(long)(d + 1) * HW + row_lo] = accO[nt][1] * inv_lo;
        ob[(long)d * HW + row_hi]       = accO[nt][2] * inv_hi;
        ob[(long)(d + 1) * HW + row_hi] = accO[nt][3] * inv_hi;
    }
}

// ---------------------------------------------------------------------------
extern "C" void kernel_launch(void* const* d_in, const int* in_sizes, int n_in,
                              void* d_out, int out_size)
{
    const float* x        = (const float*)d_in[0];
    const float* cv1_w    = (const float*)d_in[1];
    const float* cv1_bn   = (const float*)d_in[2];
    const float* cv2_w    = (const float*)d_in[3];
    const float* cv2_bn   = (const float*)d_in[4];
    const float* m_cv1_w  = (const float*)d_in[5];
    const float* m_cv1_bn = (const float*)d_in[6];
    const float* m_qkv_w  = (const float*)d_in[7];
    const float* m_rw     = (const float*)d_in[8];
    const float* m_rh     = (const float*)d_in[9];
    const float* m_cv2_w  = (const float*)d_in[10];
    const float* m_cv2_bn = (const float*)d_in[11];
    float* out = (float*)d_out;

    float *cat, *z, *qkv, *att, *w3, *part;
    cudaGetSymbolAddress((void**)&cat,  g_cat);
    cudaGetSymbolAddress((void**)&z,    g_z);
    cudaGetSymbolAddress((void**)&qkv,  g_qkv);
    cudaGetSymbolAddress((void**)&att,  g_att);
    cudaGetSymbolAddress((void**)&w3,   g_w3);
    cudaGetSymbolAddress((void**)&part, g_part);

    const int FA_SMEM = FA_TOT * 4;
    cudaFuncSetAttribute(flash_tf32_kernel,
                         cudaFuncAttributeMaxDynamicSharedMemorySize, FA_SMEM);

    const long CAT_S = 1024L * HW;
    const long RED_N = (long)BATCH * 256 * HW / 4;

    reorder_w3_kernel<<<(2 * 9 * 65536 + 255) / 256, 256>>>(m_cv1_w, w3);

    // cv1: x (512) -> cat[0:512)
    gemm_tf32_kernel<<<dim3(8, 4, BATCH), 256>>>(
        x, cv1_w, cv1_bn, nullptr, cat,
        512, 512, 512L * HW, CAT_S, 0, 3);

    for (int i = 0; i < 2; i++) {
        const float* yin = cat + (long)(256 + i * 256) * HW;

        // 3x3 conv, tap-split into 3 partials, then fused reduce+BN+SiLU
        conv3_part_kernel<<<dim3(8, 6, BATCH), 256>>>(
            yin, w3 + (long)i * 9 * 65536, part, CAT_S);
        tap_reduce_kernel<<<(int)((RED_N + 255) / 256), 256>>>(
            part, m_cv1_bn + i * 4 * 256, z);

        gemm_tf32_kernel<<<dim3(8, 6, BATCH), 256>>>(
            z, m_qkv_w + (long)i * 768 * 256, nullptr, nullptr, qkv,
            256, 768, 256L * HW, 768L * HW, 0, 0);

        flash_tf32_kernel<<<dim3(16, 4, BATCH), 256, FA_SMEM>>>(
            qkv, m_rw + i * 8192, m_rh + i * 8192, att);

        gemm_tf32_kernel<<<dim3(8, 2, BATCH), 256>>>(
            att, m_cv2_w + (long)i * 256 * 256, m_cv2_bn + i * 4 * 256,
            yin, cat + (long)(512 + i * 256) * HW,
            256, 256, 256L * HW, CAT_S, CAT_S, 7);
    }

    // cv2: cat (1024) -> out (512)
    gemm_tf32_kernel<<<dim3(8, 4, BATCH), 256>>>(
        cat, cv2_w, cv2_bn, nullptr, out,
        1024, 512, CAT_S, 512L * HW, 0, 3);
}